// round 12
// baseline (speedup 1.0000x reference)
#include <cuda_runtime.h>
#include <cuda_bf16.h>
#include <cstdint>

#define B_   2
#define S_   2048
#define H_   2048
#define NH_  16
#define HD_  128
#define M_   (B_ * S_)
#define BH_  (B_ * NH_)

// ---------------------------------------------------------------------------
// Device-global scratch (hi plane at [0], lo plane at [1])
// ---------------------------------------------------------------------------
__device__ __nv_bfloat16 g_wt2[4][2][(size_t)H_ * H_];     // WT[n][k], split
__device__ __nv_bfloat16 g_x2[2][(size_t)M_ * H_];         // batch, split
__device__ __nv_bfloat16 g_q2[2][(size_t)BH_ * S_ * HD_];  // [b,h,s,d]
__device__ __nv_bfloat16 g_k2[2][(size_t)BH_ * S_ * HD_];  // [b,h,s,d]
__device__ __nv_bfloat16 g_vT2[2][(size_t)BH_ * HD_ * S_]; // [b,h,d,s]
__device__ __nv_bfloat16 g_at2[2][(size_t)BH_ * S_ * HD_]; // [b,h,s,d]

static constexpr size_t LO_QKVA = (size_t)BH_ * S_ * HD_;  // plane stride (elems)

// ---------------------------------------------------------------------------
// PTX helpers
// ---------------------------------------------------------------------------
__device__ __forceinline__ uint32_t smem_u32(const void* p) {
    uint32_t a;
    asm("{ .reg .u64 t; cvta.to.shared.u64 t, %1; cvt.u32.u64 %0, t; }" : "=r"(a) : "l"(p));
    return a;
}

__device__ __forceinline__ void ldm4(uint32_t* r, uint32_t addr) {
    asm volatile("ldmatrix.sync.aligned.m8n8.x4.shared.b16 {%0,%1,%2,%3}, [%4];"
        : "=r"(r[0]), "=r"(r[1]), "=r"(r[2]), "=r"(r[3]) : "r"(addr));
}

__device__ __forceinline__ void mma_bf16(float* c, const uint32_t* a, const uint32_t* b) {
    asm volatile(
        "mma.sync.aligned.m16n8k16.row.col.f32.bf16.bf16.f32 "
        "{%0,%1,%2,%3}, {%4,%5,%6,%7}, {%8,%9}, {%0,%1,%2,%3};"
        : "+f"(c[0]), "+f"(c[1]), "+f"(c[2]), "+f"(c[3])
        : "r"(a[0]), "r"(a[1]), "r"(a[2]), "r"(a[3]), "r"(b[0]), "r"(b[1]));
}

#define CP16(dst, src)  asm volatile("cp.async.cg.shared.global [%0], [%1], 16;" :: "r"(dst), "l"(src))
#define CP_COMMIT()     asm volatile("cp.async.commit_group;" ::: "memory")
#define CP_WAIT0()      asm volatile("cp.async.wait_group 0;" ::: "memory")
#define CP_WAIT1()      asm volatile("cp.async.wait_group 1;" ::: "memory")

// fp32 -> bf16 hi + bf16 lo (packed pair)
__device__ __forceinline__ void split2(float a, float b, uint32_t& hi, uint32_t& lo) {
    __nv_bfloat162 h = __floats2bfloat162_rn(a, b);
    __nv_bfloat162 l = __floats2bfloat162_rn(a - __bfloat162float(h.x), b - __bfloat162float(h.y));
    hi = *reinterpret_cast<uint32_t*>(&h);
    lo = *reinterpret_cast<uint32_t*>(&l);
}
__device__ __forceinline__ void split1(float v, __nv_bfloat16& h, __nv_bfloat16& l) {
    h = __float2bfloat16_rn(v);
    l = __float2bfloat16_rn(v - __bfloat162float(h));
}

// ---------------------------------------------------------------------------
// GEMM core (qkv/out): 128x128 tile, BK=32 bf16 hi/lo, 3-stage cp.async pipe
// Stage: Ahi +0 | Alo +10240 | Bhi +20480 | Blo +30720 ; row stride 80 B
// ---------------------------------------------------------------------------
static constexpr int TILE_B  = 10240;
static constexpr int STAGE_B = 4 * TILE_B;
static constexpr int SMEM_G  = 3 * STAGE_B;   // 122880 (3 stages)

__device__ __forceinline__ void cpa_ab(uint32_t sb, int stage,
                                       const __nv_bfloat16* asrc, size_t lda, size_t aLO,
                                       const __nv_bfloat16* bsrc, size_t ldb, size_t bLO, int tid) {
    uint32_t base = sb + (uint32_t)stage * STAGE_B;
#pragma unroll
    for (int i = 0; i < 2; ++i) {
        int idx = tid + (i << 8), r = idx >> 2, c = idx & 3;
        const __nv_bfloat16* as = asrc + (size_t)r * lda + c * 8;
        uint32_t ad = base + (uint32_t)(r * 80 + c * 16);
        CP16(ad, as); CP16(ad + TILE_B, as + aLO);
        const __nv_bfloat16* bs = bsrc + (size_t)r * ldb + c * 8;
        uint32_t bd = base + 2u * TILE_B + (uint32_t)(r * 80 + c * 16);
        CP16(bd, bs); CP16(bd + TILE_B, bs + bLO);
    }
}

// One BK=32 stage of split-bf16 MMAs. acc = 64x32 warp tile.
__device__ __forceinline__ void compute_stage(uint32_t stage_base, uint32_t aoff, uint32_t boff,
                                              float acc[4][4][4]) {
#pragma unroll
    for (int kk = 0; kk < 2; ++kk) {
        uint32_t ah[4][4], al[4][4];
        uint32_t ab = stage_base + aoff + kk * 32u;
#pragma unroll
        for (int i = 0; i < 4; ++i) {
            ldm4(ah[i], ab + (uint32_t)i * 1280u);
            ldm4(al[i], ab + (uint32_t)TILE_B + (uint32_t)i * 1280u);
        }
        uint32_t bb = stage_base + 2u * TILE_B + boff + kk * 32u;
#pragma unroll
        for (int s2 = 0; s2 < 2; ++s2) {
            uint32_t th[4], tl[4];
            ldm4(th, bb + (uint32_t)s2 * 1280u);
            ldm4(tl, bb + (uint32_t)TILE_B + (uint32_t)s2 * 1280u);
            uint32_t b0[2] = { th[0], th[1] }, b1[2] = { th[2], th[3] };
            uint32_t c0[2] = { tl[0], tl[1] }, c1[2] = { tl[2], tl[3] };
#pragma unroll
            for (int i = 0; i < 4; ++i) {
                mma_bf16(acc[i][2 * s2],     ah[i], b0);
                mma_bf16(acc[i][2 * s2],     ah[i], c0);
                mma_bf16(acc[i][2 * s2],     al[i], b0);
                mma_bf16(acc[i][2 * s2 + 1], ah[i], b1);
                mma_bf16(acc[i][2 * s2 + 1], ah[i], c1);
                mma_bf16(acc[i][2 * s2 + 1], al[i], b1);
            }
        }
    }
}

template <int NIT, typename AF, typename BF>
__device__ __forceinline__ void gemm_run3(char* smem, int tid, AF af, size_t lda, size_t aLO,
                                          BF bf, size_t ldb, size_t bLO, float acc[4][4][4]) {
    const int lane = tid & 31, wid = tid >> 5;
    const int wm = (wid >> 2) * 64, wn = (wid & 3) * 32;
    const uint32_t aoff = (uint32_t)((wm + (lane & 7) + ((lane >> 3) & 1) * 8) * 80 + (lane >> 4) * 16);
    const uint32_t boff = (uint32_t)((wn + (lane & 7) + (lane >> 4) * 8) * 80 + ((lane >> 3) & 1) * 16);
    const uint32_t sb = smem_u32(smem);

#pragma unroll
    for (int i = 0; i < 4; ++i)
#pragma unroll
        for (int j = 0; j < 4; ++j)
#pragma unroll
            for (int e = 0; e < 4; ++e) acc[i][j][e] = 0.0f;

    // Prologue: stages 0 and 1 in flight (one commit group each)
    cpa_ab(sb, 0, af(0), lda, aLO, bf(0), ldb, bLO, tid); CP_COMMIT();
    cpa_ab(sb, 1, af(1), lda, aLO, bf(1), ldb, bLO, tid); CP_COMMIT();

    int cs = 2;   // next stage slot to fill
    int ps = 0;   // stage slot to compute
    for (int it = 0; it < NIT; ++it) {
        // stage `it` must be resident; allow ONE newer load in flight
        if (it + 1 < NIT) CP_WAIT1(); else CP_WAIT0();
        __syncthreads();   // all warps done computing stage it-1 -> slot cs reusable
        if (it + 2 < NIT) {
            cpa_ab(sb, cs, af(it + 2), lda, aLO, bf(it + 2), ldb, bLO, tid);
            CP_COMMIT();
            if (++cs == 3) cs = 0;
        }
        compute_stage(sb + (uint32_t)ps * STAGE_B, aoff, boff, acc);
        if (++ps == 3) ps = 0;
    }
}

// ---------------------------------------------------------------------------
// Prep: x -> bf16 hi/lo
// ---------------------------------------------------------------------------
__global__ __launch_bounds__(256)
void prep_x(const float* __restrict__ x) {
    size_t i = ((size_t)blockIdx.x * 256 + threadIdx.x) * 4;
    float4 v = *(const float4*)(x + i);
    uint32_t h0, l0, h1, l1;
    split2(v.x, v.y, h0, l0);
    split2(v.z, v.w, h1, l1);
    *(uint32_t*)(&g_x2[0][i])     = h0; *(uint32_t*)(&g_x2[0][i + 2]) = h1;
    *(uint32_t*)(&g_x2[1][i])     = l0; *(uint32_t*)(&g_x2[1][i + 2]) = l1;
}

// ---------------------------------------------------------------------------
// Weight transpose + split: g_wt2[z][.][n][k] = split(W_z[k][n])
// ---------------------------------------------------------------------------
__global__ __launch_bounds__(256)
void transpose_w(const float* __restrict__ wq, const float* __restrict__ wk,
                 const float* __restrict__ wv, const float* __restrict__ wo) {
    int z = blockIdx.z;
    const float* src = (z == 0) ? wq : (z == 1) ? wk : (z == 2) ? wv : wo;
    __shared__ float t[32][33];
    int x0 = blockIdx.x * 32, y0 = blockIdx.y * 32;
    int tx = threadIdx.x, ty = threadIdx.y;
#pragma unroll
    for (int j = 0; j < 32; j += 8)
        t[ty + j][tx] = src[(size_t)(y0 + ty + j) * H_ + x0 + tx];
    __syncthreads();
#pragma unroll
    for (int j = 0; j < 32; j += 8) {
        __nv_bfloat16 h, l;
        split1(t[tx][ty + j], h, l);
        size_t o = (size_t)(x0 + ty + j) * H_ + y0 + tx;
        g_wt2[z][0][o] = h;
        g_wt2[z][1][o] = l;
    }
}

// ---------------------------------------------------------------------------
// Kernel 1: QKV projections. grid (16, 32, 3), 128x128 tiles.
// Q,K -> hi/lo [b,h,s,d]; V -> hi/lo [b,h,d,s].
// ---------------------------------------------------------------------------
__global__ __launch_bounds__(256)
void qkv_mma(const float* __restrict__ bq, const float* __restrict__ bk,
             const float* __restrict__ bv) {
    extern __shared__ char smem[];
    const int tid = threadIdx.x, lane = tid & 31, wid = tid >> 5;
    const int wm = (wid >> 2) * 64, wn = (wid & 3) * 32;
    const int z = blockIdx.z, h = blockIdx.x, m0 = blockIdx.y * 128, n0 = h * 128;
    const float* bias = (z == 0) ? bq : (z == 1) ? bk : bv;

    float acc[4][4][4];
    gemm_run3<64>(smem, tid,
        [&](int it) { return &g_x2[0][(size_t)m0 * H_ + it * 32]; }, (size_t)H_, (size_t)M_ * H_,
        [&](int it) { return &g_wt2[z][0][(size_t)n0 * H_ + it * 32]; }, (size_t)H_, (size_t)H_ * H_,
        acc);

    const int bb = m0 >> 11, s0 = m0 & (S_ - 1);
    if (z < 2) {
        __nv_bfloat16* base = ((z == 0) ? g_q2[0] : g_k2[0]) + (size_t)(bb * NH_ + h) * S_ * HD_;
#pragma unroll
        for (int i = 0; i < 4; ++i)
#pragma unroll
            for (int j = 0; j < 4; ++j)
#pragma unroll
                for (int hf = 0; hf < 2; ++hf) {
                    int s = s0 + wm + i * 16 + (lane >> 2) + hf * 8;
                    int d = wn + j * 8 + ((lane & 3) << 1);
                    uint32_t hh, ll;
                    split2(acc[i][j][hf * 2] + bias[n0 + d],
                           acc[i][j][hf * 2 + 1] + bias[n0 + d + 1], hh, ll);
                    *(uint32_t*)(base + (size_t)s * HD_ + d)            = hh;
                    *(uint32_t*)(base + LO_QKVA + (size_t)s * HD_ + d)  = ll;
                }
    } else {
        __nv_bfloat16* vb = g_vT2[0] + (size_t)(bb * NH_ + h) * HD_ * S_;
#pragma unroll
        for (int i = 0; i < 4; ++i)
#pragma unroll
            for (int j = 0; j < 4; ++j)
#pragma unroll
                for (int hf = 0; hf < 2; ++hf) {
                    int s = s0 + wm + i * 16 + (lane >> 2) + hf * 8;
                    int d = wn + j * 8 + ((lane & 3) << 1);
                    __nv_bfloat16 h0, l0, h1, l1;
                    split1(acc[i][j][hf * 2] + bias[n0 + d], h0, l0);
                    split1(acc[i][j][hf * 2 + 1] + bias[n0 + d + 1], h1, l1);
                    vb[(size_t)d * S_ + s]                 = h0;
                    vb[LO_QKVA + (size_t)d * S_ + s]       = l0;
                    vb[(size_t)(d + 1) * S_ + s]           = h1;
                    vb[LO_QKVA + (size_t)(d + 1) * S_ + s] = l1;
                }
    }
}

// ---------------------------------------------------------------------------
// Flash attention: fused scores + softmax + PV. grid (16 qblocks, 32 z).
// (unchanged: 54.5% tensor, stable 703 us)
// ---------------------------------------------------------------------------
static constexpr int QPL  = 128 * 272;
static constexpr int KPL  = 64 * 272;
static constexpr int VPL  = 128 * 144;
static constexpr int FSTG = 2 * KPL + 2 * VPL;
static constexpr int SOFF = 2 * QPL;
static constexpr int SMEM_F = SOFF + 2 * FSTG;    // 212992

__device__ __forceinline__ void load_kv(uint32_t stg, const __nv_bfloat16* Kh,
                                        const __nv_bfloat16* Vh, int s0, int tid) {
#pragma unroll
    for (int i = 0; i < 4; ++i) {
        int idx = tid + (i << 8);
        {
            int r = idx >> 4, c = idx & 15;
            const __nv_bfloat16* s = Kh + (size_t)(s0 + r) * HD_ + c * 8;
            uint32_t d = stg + (uint32_t)(r * 272 + c * 16);
            CP16(d, s); CP16(d + KPL, s + LO_QKVA);
        }
        {
            int r = idx >> 3, c = idx & 7;
            const __nv_bfloat16* s = Vh + (size_t)r * S_ + s0 + c * 8;
            uint32_t d = stg + 2u * KPL + (uint32_t)(r * 144 + c * 16);
            CP16(d, s); CP16(d + VPL, s + LO_QKVA);
        }
    }
}

__global__ __launch_bounds__(256)
void flash_attn(const float* __restrict__ mask) {
    extern __shared__ char smem[];
    const int tid = threadIdx.x, lane = tid & 31, wid = tid >> 5;
    const int q0 = blockIdx.x * 128, z = blockIdx.y, bb = z >> 4;
    const uint32_t sb = smem_u32(smem);
    const __nv_bfloat16* Qh = g_q2[0] + (size_t)z * S_ * HD_;
    const __nv_bfloat16* Kh = g_k2[0] + (size_t)z * S_ * HD_;
    const __nv_bfloat16* Vh = g_vT2[0] + (size_t)z * HD_ * S_;

#pragma unroll
    for (int i = 0; i < 8; ++i) {
        int idx = tid + (i << 8), r = idx >> 4, c = idx & 15;
        const __nv_bfloat16* s = Qh + (size_t)(q0 + r) * HD_ + c * 8;
        uint32_t d = sb + (uint32_t)(r * 272 + c * 16);
        CP16(d, s); CP16(d + QPL, s + LO_QKVA);
    }
    load_kv(sb + SOFF, Kh, Vh, 0, tid);
    CP_COMMIT(); CP_WAIT0(); __syncthreads();

    uint32_t aqh[8][4], aql[8][4];
    {
        uint32_t qb = sb + (uint32_t)((wid * 16 + (lane & 15)) * 272 + (lane >> 4) * 16);
#pragma unroll
        for (int kk = 0; kk < 8; ++kk) {
            ldm4(aqh[kk], qb + (uint32_t)kk * 32);
            ldm4(aql[kk], qb + QPL + (uint32_t)kk * 32);
        }
    }

    float acc_o[16][4];
#pragma unroll
    for (int j = 0; j < 16; ++j)
#pragma unroll
        for (int e = 0; e < 4; ++e) acc_o[j][e] = 0.0f;
    float l0 = 0.0f, l1 = 0.0f, m0p = -1e30f, m1p = -1e30f;
    const float SC = 0.08838834764831845f;

    const int qr = q0 + wid * 16 + (lane >> 2);
    const float* mrow = mask + ((size_t)bb * S_ + qr) * S_ + ((lane & 3) << 1);

    const uint32_t koff = (uint32_t)(((lane & 7) + ((lane >> 4) << 3)) * 272 + ((lane >> 3) & 1) * 16);
    const uint32_t voff = (uint32_t)(((lane & 7) + ((lane >> 4) << 3)) * 144 + ((lane >> 3) & 1) * 16);

    for (int kb = 0; kb < 32; ++kb) {
        int cur = kb & 1;
        if (kb + 1 < 32) {
            load_kv(sb + SOFF + (uint32_t)(cur ^ 1) * FSTG, Kh, Vh, (kb + 1) * 64, tid);
            CP_COMMIT();
        }
        float mk0[8][2], mk1[8][2];
        {
            const float* mp = mrow + kb * 64;
#pragma unroll
            for (int j = 0; j < 8; ++j) {
                float2 u = *(const float2*)(mp + j * 8);
                float2 v = *(const float2*)(mp + 8 * (size_t)S_ + j * 8);
                mk0[j][0] = u.x; mk0[j][1] = u.y;
                mk1[j][0] = v.x; mk1[j][1] = v.y;
            }
        }
        uint32_t stg = sb + SOFF + (uint32_t)cur * FSTG;

        float ps[8][4];
#pragma unroll
        for (int j = 0; j < 8; ++j) { ps[j][0] = ps[j][1] = ps[j][2] = ps[j][3] = 0.0f; }
        uint32_t ka = stg + koff;
#pragma unroll
        for (int kk = 0; kk < 8; ++kk) {
#pragma unroll
            for (int s2 = 0; s2 < 4; ++s2) {
                uint32_t th[4], tl[4];
                ldm4(th, ka + (uint32_t)(s2 * 16 * 272) + (uint32_t)kk * 32);
                ldm4(tl, ka + KPL + (uint32_t)(s2 * 16 * 272) + (uint32_t)kk * 32);
                uint32_t b0[2] = { th[0], th[1] }, b1[2] = { th[2], th[3] };
                uint32_t c0[2] = { tl[0], tl[1] }, c1[2] = { tl[2], tl[3] };
                mma_bf16(ps[2 * s2],     aqh[kk], b0);
                mma_bf16(ps[2 * s2],     aqh[kk], c0);
                mma_bf16(ps[2 * s2],     aql[kk], b0);
                mma_bf16(ps[2 * s2 + 1], aqh[kk], b1);
                mma_bf16(ps[2 * s2 + 1], aqh[kk], c1);
                mma_bf16(ps[2 * s2 + 1], aql[kk], b1);
            }
        }

        float mx0 = -1e30f, mx1 = -1e30f;
#pragma unroll
        for (int j = 0; j < 8; ++j) {
            ps[j][0] = ps[j][0] * SC + mk0[j][0];
            ps[j][1] = ps[j][1] * SC + mk0[j][1];
            ps[j][2] = ps[j][2] * SC + mk1[j][0];
            ps[j][3] = ps[j][3] * SC + mk1[j][1];
            mx0 = fmaxf(mx0, fmaxf(ps[j][0], ps[j][1]));
            mx1 = fmaxf(mx1, fmaxf(ps[j][2], ps[j][3]));
        }
        mx0 = fmaxf(mx0, __shfl_xor_sync(0xffffffffu, mx0, 1));
        mx0 = fmaxf(mx0, __shfl_xor_sync(0xffffffffu, mx0, 2));
        mx1 = fmaxf(mx1, __shfl_xor_sync(0xffffffffu, mx1, 1));
        mx1 = fmaxf(mx1, __shfl_xor_sync(0xffffffffu, mx1, 2));
        float mn0 = fmaxf(m0p, mx0), mn1 = fmaxf(m1p, mx1);
        float f0 = __expf(m0p - mn0), f1 = __expf(m1p - mn1);
        float sa0 = 0.0f, sa1 = 0.0f;
#pragma unroll
        for (int j = 0; j < 8; ++j) {
            ps[j][0] = __expf(ps[j][0] - mn0); sa0 += ps[j][0];
            ps[j][1] = __expf(ps[j][1] - mn0); sa0 += ps[j][1];
            ps[j][2] = __expf(ps[j][2] - mn1); sa1 += ps[j][2];
            ps[j][3] = __expf(ps[j][3] - mn1); sa1 += ps[j][3];
        }
        sa0 += __shfl_xor_sync(0xffffffffu, sa0, 1);
        sa0 += __shfl_xor_sync(0xffffffffu, sa0, 2);
        sa1 += __shfl_xor_sync(0xffffffffu, sa1, 1);
        sa1 += __shfl_xor_sync(0xffffffffu, sa1, 2);
        l0 = l0 * f0 + sa0; l1 = l1 * f1 + sa1;
        m0p = mn0; m1p = mn1;
#pragma unroll
        for (int j = 0; j < 16; ++j) {
            acc_o[j][0] *= f0; acc_o[j][1] *= f0;
            acc_o[j][2] *= f1; acc_o[j][3] *= f1;
        }

        uint32_t va = stg + 2u * KPL + voff;
#pragma unroll
        for (int kk2 = 0; kk2 < 4; ++kk2) {
            uint32_t pah[4], pal[4];
            split2(ps[2 * kk2][0],     ps[2 * kk2][1],     pah[0], pal[0]);
            split2(ps[2 * kk2][2],     ps[2 * kk2][3],     pah[1], pal[1]);
            split2(ps[2 * kk2 + 1][0], ps[2 * kk2 + 1][1], pah[2], pal[2]);
            split2(ps[2 * kk2 + 1][2], ps[2 * kk2 + 1][3], pah[3], pal[3]);
#pragma unroll
            for (int s2 = 0; s2 < 8; ++s2) {
                uint32_t th[4], tl[4];
                ldm4(th, va + (uint32_t)(s2 * 16 * 144) + (uint32_t)kk2 * 32);
                ldm4(tl, va + VPL + (uint32_t)(s2 * 16 * 144) + (uint32_t)kk2 * 32);
                uint32_t b0[2] = { th[0], th[1] }, b1[2] = { th[2], th[3] };
                uint32_t c0[2] = { tl[0], tl[1] }, c1[2] = { tl[2], tl[3] };
                mma_bf16(acc_o[2 * s2],     pah, b0);
                mma_bf16(acc_o[2 * s2],     pah, c0);
                mma_bf16(acc_o[2 * s2],     pal, b0);
                mma_bf16(acc_o[2 * s2 + 1], pah, b1);
                mma_bf16(acc_o[2 * s2 + 1], pah, c1);
                mma_bf16(acc_o[2 * s2 + 1], pal, b1);
            }
        }
        CP_WAIT0(); __syncthreads();
    }

    float i0 = 1.0f / l0, i1 = 1.0f / l1;
    __nv_bfloat16* Ah = g_at2[0] + (size_t)z * S_ * HD_;
    int sr = q0 + wid * 16 + (lane >> 2);
#pragma unroll
    for (int j2 = 0; j2 < 16; ++j2) {
        int d = j2 * 8 + ((lane & 3) << 1);
        uint32_t hh, ll;
        split2(acc_o[j2][0] * i0, acc_o[j2][1] * i0, hh, ll);
        *(uint32_t*)(Ah + (size_t)sr * HD_ + d)           = hh;
        *(uint32_t*)(Ah + LO_QKVA + (size_t)sr * HD_ + d) = ll;
        split2(acc_o[j2][2] * i1, acc_o[j2][3] * i1, hh, ll);
        *(uint32_t*)(Ah + (size_t)(sr + 8) * HD_ + d)           = hh;
        *(uint32_t*)(Ah + LO_QKVA + (size_t)(sr + 8) * HD_ + d) = ll;
    }
}

// ---------------------------------------------------------------------------
// Kernel 3: out = gather(attn) @ W_O + b_O.  grid (16, 32)
// ---------------------------------------------------------------------------
__global__ __launch_bounds__(256)
void out_mma(const float* __restrict__ bo, float* __restrict__ out) {
    extern __shared__ char smem[];
    const int tid = threadIdx.x, lane = tid & 31, wid = tid >> 5;
    const int wm = (wid >> 2) * 64, wn = (wid & 3) * 32;
    const int n0 = blockIdx.x * 128, m0 = blockIdx.y * 128;
    const int bb = m0 >> 11, s0 = m0 & (S_ - 1);

    float acc[4][4][4];
    gemm_run3<64>(smem, tid,
        [&](int it) {
            int h = it >> 2, dbase = (it & 3) * 32;
            return &g_at2[0][((size_t)(bb * NH_ + h) * S_ + s0) * HD_ + dbase];
        }, (size_t)HD_, LO_QKVA,
        [&](int it) { return &g_wt2[3][0][(size_t)n0 * H_ + it * 32]; }, (size_t)H_, (size_t)H_ * H_,
        acc);

#pragma unroll
    for (int i = 0; i < 4; ++i)
#pragma unroll
        for (int j = 0; j < 4; ++j)
#pragma unroll
            for (int hf = 0; hf < 2; ++hf) {
                int m = m0 + wm + i * 16 + (lane >> 2) + hf * 8;
                int n = n0 + wn + j * 8 + ((lane & 3) << 1);
                float2 v = make_float2(acc[i][j][hf * 2] + bo[n],
                                       acc[i][j][hf * 2 + 1] + bo[n + 1]);
                *(float2*)(out + (size_t)m * H_ + n) = v;
            }
}

// ---------------------------------------------------------------------------
// Launch
// ---------------------------------------------------------------------------
extern "C" void kernel_launch(void* const* d_in, const int* in_sizes, int n_in,
                              void* d_out, int out_size) {
    const float* batch = (const float*)d_in[0];
    const float* mask  = (const float*)d_in[1];
    const float* wq = (const float*)d_in[2]; const float* bq = (const float*)d_in[3];
    const float* wk = (const float*)d_in[4]; const float* bk = (const float*)d_in[5];
    const float* wv = (const float*)d_in[6]; const float* bv = (const float*)d_in[7];
    const float* wo = (const float*)d_in[8]; const float* bo = (const float*)d_in[9];
    float* out = (float*)d_out;

    cudaFuncSetAttribute(qkv_mma,    cudaFuncAttributeMaxDynamicSharedMemorySize, SMEM_G);
    cudaFuncSetAttribute(flash_attn, cudaFuncAttributeMaxDynamicSharedMemorySize, SMEM_F);
    cudaFuncSetAttribute(out_mma,    cudaFuncAttributeMaxDynamicSharedMemorySize, SMEM_G);

    int prep_blocks = (int)(((size_t)M_ * H_ / 4 + 255) / 256);
    prep_x<<<prep_blocks, 256>>>(batch);
    transpose_w<<<dim3(64, 64, 4), dim3(32, 8)>>>(wq, wk, wv, wo);
    qkv_mma<<<dim3(16, 32, 3), 256, SMEM_G>>>(bq, bk, bv);
    flash_attn<<<dim3(16, 32), 256, SMEM_F>>>(mask);
    out_mma<<<dim3(16, 32), 256, SMEM_G>>>(bo, out);
}

// round 14
// speedup vs baseline: 1.0774x; 1.0774x over previous
#include <cuda_runtime.h>
#include <cuda_bf16.h>
#include <cstdint>

#define B_   2
#define S_   2048
#define H_   2048
#define NH_  16
#define HD_  128
#define M_   (B_ * S_)
#define BH_  (B_ * NH_)

// ---------------------------------------------------------------------------
// Device-global scratch (hi plane at [0], lo plane at [1])
// ---------------------------------------------------------------------------
__device__ __nv_bfloat16 g_wt2[4][2][(size_t)H_ * H_];     // WT[n][k], split
__device__ __nv_bfloat16 g_x2[2][(size_t)M_ * H_];         // batch, split
__device__ __nv_bfloat16 g_q2[2][(size_t)BH_ * S_ * HD_];  // [b,h,s,d]
__device__ __nv_bfloat16 g_k2[2][(size_t)BH_ * S_ * HD_];  // [b,h,s,d]
__device__ __nv_bfloat16 g_vT2[2][(size_t)BH_ * HD_ * S_]; // [b,h,d,s]
__device__ __nv_bfloat16 g_at2[2][(size_t)BH_ * S_ * HD_]; // [b,h,s,d]

static constexpr size_t LO_QKVA = (size_t)BH_ * S_ * HD_;  // plane stride (elems)

// ---------------------------------------------------------------------------
// PTX helpers
// ---------------------------------------------------------------------------
__device__ __forceinline__ uint32_t smem_u32(const void* p) {
    uint32_t a;
    asm("{ .reg .u64 t; cvta.to.shared.u64 t, %1; cvt.u32.u64 %0, t; }" : "=r"(a) : "l"(p));
    return a;
}

__device__ __forceinline__ void ldm4(uint32_t* r, uint32_t addr) {
    asm volatile("ldmatrix.sync.aligned.m8n8.x4.shared.b16 {%0,%1,%2,%3}, [%4];"
        : "=r"(r[0]), "=r"(r[1]), "=r"(r[2]), "=r"(r[3]) : "r"(addr));
}

__device__ __forceinline__ void mma_bf16(float* c, const uint32_t* a, const uint32_t* b) {
    asm volatile(
        "mma.sync.aligned.m16n8k16.row.col.f32.bf16.bf16.f32 "
        "{%0,%1,%2,%3}, {%4,%5,%6,%7}, {%8,%9}, {%0,%1,%2,%3};"
        : "+f"(c[0]), "+f"(c[1]), "+f"(c[2]), "+f"(c[3])
        : "r"(a[0]), "r"(a[1]), "r"(a[2]), "r"(a[3]), "r"(b[0]), "r"(b[1]));
}

#define CP16(dst, src)  asm volatile("cp.async.cg.shared.global [%0], [%1], 16;" :: "r"(dst), "l"(src))
#define CP_COMMIT()     asm volatile("cp.async.commit_group;" ::: "memory")
#define CP_WAIT0()      asm volatile("cp.async.wait_group 0;" ::: "memory")

// fp32 -> bf16 hi + bf16 lo (packed pair)
__device__ __forceinline__ void split2(float a, float b, uint32_t& hi, uint32_t& lo) {
    __nv_bfloat162 h = __floats2bfloat162_rn(a, b);
    __nv_bfloat162 l = __floats2bfloat162_rn(a - __bfloat162float(h.x), b - __bfloat162float(h.y));
    hi = *reinterpret_cast<uint32_t*>(&h);
    lo = *reinterpret_cast<uint32_t*>(&l);
}
__device__ __forceinline__ void split1(float v, __nv_bfloat16& h, __nv_bfloat16& l) {
    h = __float2bfloat16_rn(v);
    l = __float2bfloat16_rn(v - __bfloat162float(h));
}

// ---------------------------------------------------------------------------
// GEMM core (qkv/out): EXACT R8 config. 128x128 tile, BK=32 bf16 hi/lo,
// cp.async double buffer, SMEM 81920 -> 2 CTAs/SM naturally.
// Stage: Ahi +0 | Alo +10240 | Bhi +20480 | Blo +30720 ; row stride 80 B
// ---------------------------------------------------------------------------
static constexpr int TILE_B  = 10240;
static constexpr int STAGE_B = 4 * TILE_B;
static constexpr int SMEM_G  = 2 * STAGE_B;   // 81920

__device__ __forceinline__ void cpa_ab(uint32_t sb, int stage,
                                       const __nv_bfloat16* asrc, size_t lda, size_t aLO,
                                       const __nv_bfloat16* bsrc, size_t ldb, size_t bLO, int tid) {
    uint32_t base = sb + (uint32_t)stage * STAGE_B;
#pragma unroll
    for (int i = 0; i < 2; ++i) {
        int idx = tid + (i << 8), r = idx >> 2, c = idx & 3;
        const __nv_bfloat16* as = asrc + (size_t)r * lda + c * 8;
        uint32_t ad = base + (uint32_t)(r * 80 + c * 16);
        CP16(ad, as); CP16(ad + TILE_B, as + aLO);
        const __nv_bfloat16* bs = bsrc + (size_t)r * ldb + c * 8;
        uint32_t bd = base + 2u * TILE_B + (uint32_t)(r * 80 + c * 16);
        CP16(bd, bs); CP16(bd + TILE_B, bs + bLO);
    }
}

// One BK=32 stage of split-bf16 MMAs. acc = 64x32 warp tile.
__device__ __forceinline__ void compute_stage(uint32_t stage_base, uint32_t aoff, uint32_t boff,
                                              float acc[4][4][4]) {
#pragma unroll
    for (int kk = 0; kk < 2; ++kk) {
        uint32_t ah[4][4], al[4][4];
        uint32_t ab = stage_base + aoff + kk * 32u;
#pragma unroll
        for (int i = 0; i < 4; ++i) {
            ldm4(ah[i], ab + (uint32_t)i * 1280u);
            ldm4(al[i], ab + (uint32_t)TILE_B + (uint32_t)i * 1280u);
        }
        uint32_t bb = stage_base + 2u * TILE_B + boff + kk * 32u;
#pragma unroll
        for (int s2 = 0; s2 < 2; ++s2) {
            uint32_t th[4], tl[4];
            ldm4(th, bb + (uint32_t)s2 * 1280u);
            ldm4(tl, bb + (uint32_t)TILE_B + (uint32_t)s2 * 1280u);
            uint32_t b0[2] = { th[0], th[1] }, b1[2] = { th[2], th[3] };
            uint32_t c0[2] = { tl[0], tl[1] }, c1[2] = { tl[2], tl[3] };
#pragma unroll
            for (int i = 0; i < 4; ++i) {
                mma_bf16(acc[i][2 * s2],     ah[i], b0);
                mma_bf16(acc[i][2 * s2],     ah[i], c0);
                mma_bf16(acc[i][2 * s2],     al[i], b0);
                mma_bf16(acc[i][2 * s2 + 1], ah[i], b1);
                mma_bf16(acc[i][2 * s2 + 1], ah[i], c1);
                mma_bf16(acc[i][2 * s2 + 1], al[i], b1);
            }
        }
    }
}

template <int NIT, typename AF, typename BF>
__device__ __forceinline__ void gemm_run2(char* smem, int tid, AF af, size_t lda, size_t aLO,
                                          BF bf, size_t ldb, size_t bLO, float acc[4][4][4]) {
    const int lane = tid & 31, wid = tid >> 5;
    const int wm = (wid >> 2) * 64, wn = (wid & 3) * 32;
    const uint32_t aoff = (uint32_t)((wm + (lane & 7) + ((lane >> 3) & 1) * 8) * 80 + (lane >> 4) * 16);
    const uint32_t boff = (uint32_t)((wn + (lane & 7) + (lane >> 4) * 8) * 80 + ((lane >> 3) & 1) * 16);
    const uint32_t sb = smem_u32(smem);

#pragma unroll
    for (int i = 0; i < 4; ++i)
#pragma unroll
        for (int j = 0; j < 4; ++j)
#pragma unroll
            for (int e = 0; e < 4; ++e) acc[i][j][e] = 0.0f;

    cpa_ab(sb, 0, af(0), lda, aLO, bf(0), ldb, bLO, tid);
    CP_COMMIT(); CP_WAIT0(); __syncthreads();

    for (int it = 0; it < NIT; ++it) {
        int cur = it & 1;
        if (it + 1 < NIT) {
            cpa_ab(sb, cur ^ 1, af(it + 1), lda, aLO, bf(it + 1), ldb, bLO, tid);
            CP_COMMIT();
        }
        compute_stage(sb + (uint32_t)cur * STAGE_B, aoff, boff, acc);
        CP_WAIT0(); __syncthreads();
    }
}

// ---------------------------------------------------------------------------
// Prep: x -> bf16 hi/lo
// ---------------------------------------------------------------------------
__global__ __launch_bounds__(256)
void prep_x(const float* __restrict__ x) {
    size_t i = ((size_t)blockIdx.x * 256 + threadIdx.x) * 4;
    float4 v = *(const float4*)(x + i);
    uint32_t h0, l0, h1, l1;
    split2(v.x, v.y, h0, l0);
    split2(v.z, v.w, h1, l1);
    *(uint32_t*)(&g_x2[0][i])     = h0; *(uint32_t*)(&g_x2[0][i + 2]) = h1;
    *(uint32_t*)(&g_x2[1][i])     = l0; *(uint32_t*)(&g_x2[1][i + 2]) = l1;
}

// ---------------------------------------------------------------------------
// Weight transpose + split: g_wt2[z][.][n][k] = split(W_z[k][n])
// ---------------------------------------------------------------------------
__global__ __launch_bounds__(256)
void transpose_w(const float* __restrict__ wq, const float* __restrict__ wk,
                 const float* __restrict__ wv, const float* __restrict__ wo) {
    int z = blockIdx.z;
    const float* src = (z == 0) ? wq : (z == 1) ? wk : (z == 2) ? wv : wo;
    __shared__ float t[32][33];
    int x0 = blockIdx.x * 32, y0 = blockIdx.y * 32;
    int tx = threadIdx.x, ty = threadIdx.y;
#pragma unroll
    for (int j = 0; j < 32; j += 8)
        t[ty + j][tx] = src[(size_t)(y0 + ty + j) * H_ + x0 + tx];
    __syncthreads();
#pragma unroll
    for (int j = 0; j < 32; j += 8) {
        __nv_bfloat16 h, l;
        split1(t[tx][ty + j], h, l);
        size_t o = (size_t)(x0 + ty + j) * H_ + y0 + tx;
        g_wt2[z][0][o] = h;
        g_wt2[z][1][o] = l;
    }
}

// ---------------------------------------------------------------------------
// Kernel 1: QKV projections (EXACT R8). grid (16, 32, 3).
// Q,K -> hi/lo [b,h,s,d]; V -> hi/lo [b,h,d,s].
// ---------------------------------------------------------------------------
__global__ __launch_bounds__(256)
void qkv_mma(const float* __restrict__ bq, const float* __restrict__ bk,
             const float* __restrict__ bv) {
    extern __shared__ char smem[];
    const int tid = threadIdx.x, lane = tid & 31, wid = tid >> 5;
    const int wm = (wid >> 2) * 64, wn = (wid & 3) * 32;
    const int z = blockIdx.z, h = blockIdx.x, m0 = blockIdx.y * 128, n0 = h * 128;
    const float* bias = (z == 0) ? bq : (z == 1) ? bk : bv;

    float acc[4][4][4];
    gemm_run2<64>(smem, tid,
        [&](int it) { return &g_x2[0][(size_t)m0 * H_ + it * 32]; }, (size_t)H_, (size_t)M_ * H_,
        [&](int it) { return &g_wt2[z][0][(size_t)n0 * H_ + it * 32]; }, (size_t)H_, (size_t)H_ * H_,
        acc);

    const int bb = m0 >> 11, s0 = m0 & (S_ - 1);
    if (z < 2) {
        __nv_bfloat16* base = ((z == 0) ? g_q2[0] : g_k2[0]) + (size_t)(bb * NH_ + h) * S_ * HD_;
#pragma unroll
        for (int i = 0; i < 4; ++i)
#pragma unroll
            for (int j = 0; j < 4; ++j)
#pragma unroll
                for (int hf = 0; hf < 2; ++hf) {
                    int s = s0 + wm + i * 16 + (lane >> 2) + hf * 8;
                    int d = wn + j * 8 + ((lane & 3) << 1);
                    uint32_t hh, ll;
                    split2(acc[i][j][hf * 2] + bias[n0 + d],
                           acc[i][j][hf * 2 + 1] + bias[n0 + d + 1], hh, ll);
                    *(uint32_t*)(base + (size_t)s * HD_ + d)            = hh;
                    *(uint32_t*)(base + LO_QKVA + (size_t)s * HD_ + d)  = ll;
                }
    } else {
        __nv_bfloat16* vb = g_vT2[0] + (size_t)(bb * NH_ + h) * HD_ * S_;
#pragma unroll
        for (int i = 0; i < 4; ++i)
#pragma unroll
            for (int j = 0; j < 4; ++j)
#pragma unroll
                for (int hf = 0; hf < 2; ++hf) {
                    int s = s0 + wm + i * 16 + (lane >> 2) + hf * 8;
                    int d = wn + j * 8 + ((lane & 3) << 1);
                    __nv_bfloat16 h0, l0, h1, l1;
                    split1(acc[i][j][hf * 2] + bias[n0 + d], h0, l0);
                    split1(acc[i][j][hf * 2 + 1] + bias[n0 + d + 1], h1, l1);
                    vb[(size_t)d * S_ + s]                 = h0;
                    vb[LO_QKVA + (size_t)d * S_ + s]       = l0;
                    vb[(size_t)(d + 1) * S_ + s]           = h1;
                    vb[LO_QKVA + (size_t)(d + 1) * S_ + s] = l1;
                }
    }
}

// ---------------------------------------------------------------------------
// Flash attention, software-pipelined: S(kb+1) issued between softmax(kb)
// and PV(kb) so the serial softmax chain overlaps tensor work.
// grid (16 qblocks, 32 z). K-block = 64 keys, double-buffered, split K/V groups.
// ---------------------------------------------------------------------------
static constexpr int QPL  = 128 * 272;
static constexpr int KPL  = 64 * 272;
static constexpr int VPL  = 128 * 144;
static constexpr int FSTG = 2 * KPL + 2 * VPL;
static constexpr int SOFF = 2 * QPL;
static constexpr int SMEM_F = SOFF + 2 * FSTG;    // 212992

__device__ __forceinline__ void load_k(uint32_t stg, const __nv_bfloat16* Kh, int s0, int tid) {
#pragma unroll
    for (int i = 0; i < 4; ++i) {
        int idx = tid + (i << 8);
        int r = idx >> 4, c = idx & 15;
        const __nv_bfloat16* s = Kh + (size_t)(s0 + r) * HD_ + c * 8;
        uint32_t d = stg + (uint32_t)(r * 272 + c * 16);
        CP16(d, s); CP16(d + KPL, s + LO_QKVA);
    }
}
__device__ __forceinline__ void load_v(uint32_t stg, const __nv_bfloat16* Vh, int s0, int tid) {
#pragma unroll
    for (int i = 0; i < 4; ++i) {
        int idx = tid + (i << 8);
        int r = idx >> 3, c = idx & 7;
        const __nv_bfloat16* s = Vh + (size_t)r * S_ + s0 + c * 8;
        uint32_t d = stg + 2u * KPL + (uint32_t)(r * 144 + c * 16);
        CP16(d, s); CP16(d + VPL, s + LO_QKVA);
    }
}

// S = Q K^T (3-term split). Q-hi in regs; Q-lo reloaded per kk from smem.
__device__ __forceinline__ void s_phase(uint32_t stg, uint32_t koff, uint32_t qlo_base,
                                        const uint32_t aqh[8][4], float ps[8][4]) {
#pragma unroll
    for (int j = 0; j < 8; ++j) { ps[j][0] = ps[j][1] = ps[j][2] = ps[j][3] = 0.0f; }
    uint32_t ka = stg + koff;
#pragma unroll
    for (int kk = 0; kk < 8; ++kk) {
        uint32_t aql[4];
        ldm4(aql, qlo_base + (uint32_t)kk * 32);
#pragma unroll
        for (int s2 = 0; s2 < 4; ++s2) {
            uint32_t th[4], tl[4];
            ldm4(th, ka + (uint32_t)(s2 * 16 * 272) + (uint32_t)kk * 32);
            ldm4(tl, ka + KPL + (uint32_t)(s2 * 16 * 272) + (uint32_t)kk * 32);
            uint32_t b0[2] = { th[0], th[1] }, b1[2] = { th[2], th[3] };
            uint32_t c0[2] = { tl[0], tl[1] }, c1[2] = { tl[2], tl[3] };
            mma_bf16(ps[2 * s2],     aqh[kk], b0);
            mma_bf16(ps[2 * s2],     aqh[kk], c0);
            mma_bf16(ps[2 * s2],     aql,     b0);
            mma_bf16(ps[2 * s2 + 1], aqh[kk], b1);
            mma_bf16(ps[2 * s2 + 1], aqh[kk], c1);
            mma_bf16(ps[2 * s2 + 1], aql,     b1);
        }
    }
}

__global__ __launch_bounds__(256)
void flash_attn(const float* __restrict__ mask) {
    extern __shared__ char smem[];
    const int tid = threadIdx.x, lane = tid & 31, wid = tid >> 5;
    const int q0 = blockIdx.x * 128, z = blockIdx.y, bb = z >> 4;
    const uint32_t sb = smem_u32(smem);
    const __nv_bfloat16* Qh = g_q2[0] + (size_t)z * S_ * HD_;
    const __nv_bfloat16* Kh = g_k2[0] + (size_t)z * S_ * HD_;
    const __nv_bfloat16* Vh = g_vT2[0] + (size_t)z * HD_ * S_;

    // Prologue: Q tile (hi+lo) + stage0 K/V (one group)
#pragma unroll
    for (int i = 0; i < 8; ++i) {
        int idx = tid + (i << 8), r = idx >> 4, c = idx & 15;
        const __nv_bfloat16* s = Qh + (size_t)(q0 + r) * HD_ + c * 8;
        uint32_t d = sb + (uint32_t)(r * 272 + c * 16);
        CP16(d, s); CP16(d + QPL, s + LO_QKVA);
    }
    load_k(sb + SOFF, Kh, 0, tid);
    load_v(sb + SOFF, Vh, 0, tid);
    CP_COMMIT(); CP_WAIT0(); __syncthreads();

    // Q-hi fragments resident in registers; Q-lo reloaded per use.
    const uint32_t qb = sb + (uint32_t)((wid * 16 + (lane & 15)) * 272 + (lane >> 4) * 16);
    const uint32_t qlo_base = qb + (uint32_t)QPL;
    uint32_t aqh[8][4];
#pragma unroll
    for (int kk = 0; kk < 8; ++kk) ldm4(aqh[kk], qb + (uint32_t)kk * 32);

    float acc_o[16][4];
#pragma unroll
    for (int j = 0; j < 16; ++j)
#pragma unroll
        for (int e = 0; e < 4; ++e) acc_o[j][e] = 0.0f;
    float l0 = 0.0f, l1 = 0.0f, m0p = -1e30f, m1p = -1e30f;
    const float SC = 0.08838834764831845f;

    const int qr = q0 + wid * 16 + (lane >> 2);
    const float* mrow = mask + ((size_t)bb * S_ + qr) * S_ + ((lane & 3) << 1);

    const uint32_t koff = (uint32_t)(((lane & 7) + ((lane >> 4) << 3)) * 272 + ((lane >> 3) & 1) * 16);
    const uint32_t voff = (uint32_t)(((lane & 7) + ((lane >> 4) << 3)) * 144 + ((lane >> 3) & 1) * 16);

    // Issue stage1 loads (one group), then S(0) from stage0.
    load_k(sb + SOFF + FSTG, Kh, 64, tid);
    load_v(sb + SOFF + FSTG, Vh, 64, tid);
    CP_COMMIT();

    float ps[2][8][4];
    s_phase(sb + SOFF, koff, qlo_base, aqh, ps[0]);

    for (int kb = 0; kb < 32; ++kb) {
        const int cur = kb & 1;
        float (*pc)[4] = ps[cur];

        // ---- softmax(kb) on pc ----
        float mk0[8][2], mk1[8][2];
        {
            const float* mp = mrow + kb * 64;
#pragma unroll
            for (int j = 0; j < 8; ++j) {
                float2 u = *(const float2*)(mp + j * 8);
                float2 v = *(const float2*)(mp + 8 * (size_t)S_ + j * 8);
                mk0[j][0] = u.x; mk0[j][1] = u.y;
                mk1[j][0] = v.x; mk1[j][1] = v.y;
            }
        }
        float mx0 = -1e30f, mx1 = -1e30f;
#pragma unroll
        for (int j = 0; j < 8; ++j) {
            pc[j][0] = pc[j][0] * SC + mk0[j][0];
            pc[j][1] = pc[j][1] * SC + mk0[j][1];
            pc[j][2] = pc[j][2] * SC + mk1[j][0];
            pc[j][3] = pc[j][3] * SC + mk1[j][1];
            mx0 = fmaxf(mx0, fmaxf(pc[j][0], pc[j][1]));
            mx1 = fmaxf(mx1, fmaxf(pc[j][2], pc[j][3]));
        }
        mx0 = fmaxf(mx0, __shfl_xor_sync(0xffffffffu, mx0, 1));
        mx0 = fmaxf(mx0, __shfl_xor_sync(0xffffffffu, mx0, 2));
        mx1 = fmaxf(mx1, __shfl_xor_sync(0xffffffffu, mx1, 1));
        mx1 = fmaxf(mx1, __shfl_xor_sync(0xffffffffu, mx1, 2));
        float mn0 = fmaxf(m0p, mx0), mn1 = fmaxf(m1p, mx1);
        float f0 = __expf(m0p - mn0), f1 = __expf(m1p - mn1);
        float sa0 = 0.0f, sa1 = 0.0f;
#pragma unroll
        for (int j = 0; j < 8; ++j) {
            pc[j][0] = __expf(pc[j][0] - mn0); sa0 += pc[j][0];
            pc[j][1] = __expf(pc[j][1] - mn0); sa0 += pc[j][1];
            pc[j][2] = __expf(pc[j][2] - mn1); sa1 += pc[j][2];
            pc[j][3] = __expf(pc[j][3] - mn1); sa1 += pc[j][3];
        }
        sa0 += __shfl_xor_sync(0xffffffffu, sa0, 1);
        sa0 += __shfl_xor_sync(0xffffffffu, sa0, 2);
        sa1 += __shfl_xor_sync(0xffffffffu, sa1, 1);
        sa1 += __shfl_xor_sync(0xffffffffu, sa1, 2);
        l0 = l0 * f0 + sa0; l1 = l1 * f1 + sa1;
        m0p = mn0; m1p = mn1;
#pragma unroll
        for (int j = 0; j < 16; ++j) {
            acc_o[j][0] *= f0; acc_o[j][1] *= f0;
            acc_o[j][2] *= f1; acc_o[j][3] *= f1;
        }

        // ---- pipelined S(kb+1): overlaps the softmax chain above ----
        if (kb < 31) {
            CP_WAIT0(); __syncthreads();   // stage kb+1 resident; all warps past S(kb)
            if (kb + 2 < 32) {             // K(kb+2) -> K-region of stage cur (free)
                load_k(sb + SOFF + (uint32_t)cur * FSTG, Kh, (kb + 2) * 64, tid);
                CP_COMMIT();
            }
            s_phase(sb + SOFF + (uint32_t)(cur ^ 1) * FSTG, koff, qlo_base, aqh, ps[cur ^ 1]);
        }

        // ---- PV(kb): O += P V from stage cur ----
        uint32_t va = sb + SOFF + (uint32_t)cur * FSTG + 2u * KPL + voff;
#pragma unroll
        for (int kk2 = 0; kk2 < 4; ++kk2) {
            uint32_t pah[4], pal[4];
            split2(pc[2 * kk2][0],     pc[2 * kk2][1],     pah[0], pal[0]);
            split2(pc[2 * kk2][2],     pc[2 * kk2][3],     pah[1], pal[1]);
            split2(pc[2 * kk2 + 1][0], pc[2 * kk2 + 1][1], pah[2], pal[2]);
            split2(pc[2 * kk2 + 1][2], pc[2 * kk2 + 1][3], pah[3], pal[3]);
#pragma unroll
            for (int s2 = 0; s2 < 8; ++s2) {
                uint32_t th[4], tl[4];
                ldm4(th, va + (uint32_t)(s2 * 16 * 144) + (uint32_t)kk2 * 32);
                ldm4(tl, va + VPL + (uint32_t)(s2 * 16 * 144) + (uint32_t)kk2 * 32);
                uint32_t b0[2] = { th[0], th[1] }, b1[2] = { th[2], th[3] };
                uint32_t c0[2] = { tl[0], tl[1] }, c1[2] = { tl[2], tl[3] };
                mma_bf16(acc_o[2 * s2],     pah, b0);
                mma_bf16(acc_o[2 * s2],     pah, c0);
                mma_bf16(acc_o[2 * s2],     pal, b0);
                mma_bf16(acc_o[2 * s2 + 1], pah, b1);
                mma_bf16(acc_o[2 * s2 + 1], pah, c1);
                mma_bf16(acc_o[2 * s2 + 1], pal, b1);
            }
        }

        // ---- V(kb+2) load: V-region of stage cur is free only after PV(kb) ----
        if (kb + 2 < 32) {
            __syncthreads();               // all warps done reading V(kb)
            load_v(sb + SOFF + (uint32_t)cur * FSTG, Vh, (kb + 2) * 64, tid);
            CP_COMMIT();
        }
    }

    // ---- epilogue: O/l -> hi/lo bf16 ----
    float i0 = 1.0f / l0, i1 = 1.0f / l1;
    __nv_bfloat16* Ah = g_at2[0] + (size_t)z * S_ * HD_;
    int sr = q0 + wid * 16 + (lane >> 2);
#pragma unroll
    for (int j2 = 0; j2 < 16; ++j2) {
        int d = j2 * 8 + ((lane & 3) << 1);
        uint32_t hh, ll;
        split2(acc_o[j2][0] * i0, acc_o[j2][1] * i0, hh, ll);
        *(uint32_t*)(Ah + (size_t)sr * HD_ + d)           = hh;
        *(uint32_t*)(Ah + LO_QKVA + (size_t)sr * HD_ + d) = ll;
        split2(acc_o[j2][2] * i1, acc_o[j2][3] * i1, hh, ll);
        *(uint32_t*)(Ah + (size_t)(sr + 8) * HD_ + d)           = hh;
        *(uint32_t*)(Ah + LO_QKVA + (size_t)(sr + 8) * HD_ + d) = ll;
    }
}

// ---------------------------------------------------------------------------
// Kernel 3: out = gather(attn) @ W_O + b_O (EXACT R8).  grid (16, 32)
// ---------------------------------------------------------------------------
__global__ __launch_bounds__(256)
void out_mma(const float* __restrict__ bo, float* __restrict__ out) {
    extern __shared__ char smem[];
    const int tid = threadIdx.x, lane = tid & 31, wid = tid >> 5;
    const int wm = (wid >> 2) * 64, wn = (wid & 3) * 32;
    const int n0 = blockIdx.x * 128, m0 = blockIdx.y * 128;
    const int bb = m0 >> 11, s0 = m0 & (S_ - 1);

    float acc[4][4][4];
    gemm_run2<64>(smem, tid,
        [&](int it) {
            int h = it >> 2, dbase = (it & 3) * 32;
            return &g_at2[0][((size_t)(bb * NH_ + h) * S_ + s0) * HD_ + dbase];
        }, (size_t)HD_, LO_QKVA,
        [&](int it) { return &g_wt2[3][0][(size_t)n0 * H_ + it * 32]; }, (size_t)H_, (size_t)H_ * H_,
        acc);

#pragma unroll
    for (int i = 0; i < 4; ++i)
#pragma unroll
        for (int j = 0; j < 4; ++j)
#pragma unroll
            for (int hf = 0; hf < 2; ++hf) {
                int m = m0 + wm + i * 16 + (lane >> 2) + hf * 8;
                int n = n0 + wn + j * 8 + ((lane & 3) << 1);
                float2 v = make_float2(acc[i][j][hf * 2] + bo[n],
                                       acc[i][j][hf * 2 + 1] + bo[n + 1]);
                *(float2*)(out + (size_t)m * H_ + n) = v;
            }
}

// ---------------------------------------------------------------------------
// Launch
// ---------------------------------------------------------------------------
extern "C" void kernel_launch(void* const* d_in, const int* in_sizes, int n_in,
                              void* d_out, int out_size) {
    const float* batch = (const float*)d_in[0];
    const float* mask  = (const float*)d_in[1];
    const float* wq = (const float*)d_in[2]; const float* bq = (const float*)d_in[3];
    const float* wk = (const float*)d_in[4]; const float* bk = (const float*)d_in[5];
    const float* wv = (const float*)d_in[6]; const float* bv = (const float*)d_in[7];
    const float* wo = (const float*)d_in[8]; const float* bo = (const float*)d_in[9];
    float* out = (float*)d_out;

    cudaFuncSetAttribute(qkv_mma,    cudaFuncAttributeMaxDynamicSharedMemorySize, SMEM_G);
    cudaFuncSetAttribute(flash_attn, cudaFuncAttributeMaxDynamicSharedMemorySize, SMEM_F);
    cudaFuncSetAttribute(out_mma,    cudaFuncAttributeMaxDynamicSharedMemorySize, SMEM_G);

    int prep_blocks = (int)(((size_t)M_ * H_ / 4 + 255) / 256);
    prep_x<<<prep_blocks, 256>>>(batch);
    transpose_w<<<dim3(64, 64, 4), dim3(32, 8)>>>(wq, wk, wv, wo);
    qkv_mma<<<dim3(16, 32, 3), 256, SMEM_G>>>(bq, bk, bv);
    flash_attn<<<dim3(16, 32), 256, SMEM_F>>>(mask);
    out_mma<<<dim3(16, 32), 256, SMEM_G>>>(bo, out);
}

// round 16
// speedup vs baseline: 1.1082x; 1.0286x over previous
#include <cuda_runtime.h>
#include <cuda_bf16.h>
#include <cstdint>

#define B_   2
#define S_   2048
#define H_   2048
#define NH_  16
#define HD_  128
#define M_   (B_ * S_)
#define BH_  (B_ * NH_)

// ---------------------------------------------------------------------------
// Device-global scratch (hi plane at [0], lo plane at [1])
// ---------------------------------------------------------------------------
__device__ __nv_bfloat16 g_wt2[4][2][(size_t)H_ * H_];     // WT[n][k], split
__device__ __nv_bfloat16 g_x2[2][(size_t)M_ * H_];         // batch, split
__device__ __nv_bfloat16 g_q2[2][(size_t)BH_ * S_ * HD_];  // [b,h,s,d]
__device__ __nv_bfloat16 g_k2[2][(size_t)BH_ * S_ * HD_];  // [b,h,s,d]
__device__ __nv_bfloat16 g_vT2[2][(size_t)BH_ * HD_ * S_]; // [b,h,d,s]
__device__ __nv_bfloat16 g_at2[2][(size_t)BH_ * S_ * HD_]; // [b,h,s,d]

static constexpr size_t LO_QKVA = (size_t)BH_ * S_ * HD_;  // plane stride (elems)

// ---------------------------------------------------------------------------
// PTX helpers
// ---------------------------------------------------------------------------
__device__ __forceinline__ uint32_t smem_u32(const void* p) {
    uint32_t a;
    asm("{ .reg .u64 t; cvta.to.shared.u64 t, %1; cvt.u32.u64 %0, t; }" : "=r"(a) : "l"(p));
    return a;
}

__device__ __forceinline__ void ldm4(uint32_t* r, uint32_t addr) {
    asm volatile("ldmatrix.sync.aligned.m8n8.x4.shared.b16 {%0,%1,%2,%3}, [%4];"
        : "=r"(r[0]), "=r"(r[1]), "=r"(r[2]), "=r"(r[3]) : "r"(addr));
}

__device__ __forceinline__ void mma_bf16(float* c, const uint32_t* a, const uint32_t* b) {
    asm volatile(
        "mma.sync.aligned.m16n8k16.row.col.f32.bf16.bf16.f32 "
        "{%0,%1,%2,%3}, {%4,%5,%6,%7}, {%8,%9}, {%0,%1,%2,%3};"
        : "+f"(c[0]), "+f"(c[1]), "+f"(c[2]), "+f"(c[3])
        : "r"(a[0]), "r"(a[1]), "r"(a[2]), "r"(a[3]), "r"(b[0]), "r"(b[1]));
}

#define CP16(dst, src)  asm volatile("cp.async.cg.shared.global [%0], [%1], 16;" :: "r"(dst), "l"(src))
#define CP_COMMIT()     asm volatile("cp.async.commit_group;" ::: "memory")
#define CP_WAIT0()      asm volatile("cp.async.wait_group 0;" ::: "memory")
#define CP_WAIT1()      asm volatile("cp.async.wait_group 1;" ::: "memory")
#define CP_WAIT2()      asm volatile("cp.async.wait_group 2;" ::: "memory")

// fp32 -> bf16 hi + bf16 lo (packed pair)
__device__ __forceinline__ void split2(float a, float b, uint32_t& hi, uint32_t& lo) {
    __nv_bfloat162 h = __floats2bfloat162_rn(a, b);
    __nv_bfloat162 l = __floats2bfloat162_rn(a - __bfloat162float(h.x), b - __bfloat162float(h.y));
    hi = *reinterpret_cast<uint32_t*>(&h);
    lo = *reinterpret_cast<uint32_t*>(&l);
}
__device__ __forceinline__ void split1(float v, __nv_bfloat16& h, __nv_bfloat16& l) {
    h = __float2bfloat16_rn(v);
    l = __float2bfloat16_rn(v - __bfloat162float(h));
}

// ---------------------------------------------------------------------------
// GEMM core (qkv/out): EXACT R8 config. 128x128 tile, BK=32 bf16 hi/lo,
// cp.async double buffer, SMEM 81920 -> 2 CTAs/SM naturally.
// ---------------------------------------------------------------------------
static constexpr int TILE_B  = 10240;
static constexpr int STAGE_B = 4 * TILE_B;
static constexpr int SMEM_G  = 2 * STAGE_B;   // 81920

__device__ __forceinline__ void cpa_ab(uint32_t sb, int stage,
                                       const __nv_bfloat16* asrc, size_t lda, size_t aLO,
                                       const __nv_bfloat16* bsrc, size_t ldb, size_t bLO, int tid) {
    uint32_t base = sb + (uint32_t)stage * STAGE_B;
#pragma unroll
    for (int i = 0; i < 2; ++i) {
        int idx = tid + (i << 8), r = idx >> 2, c = idx & 3;
        const __nv_bfloat16* as = asrc + (size_t)r * lda + c * 8;
        uint32_t ad = base + (uint32_t)(r * 80 + c * 16);
        CP16(ad, as); CP16(ad + TILE_B, as + aLO);
        const __nv_bfloat16* bs = bsrc + (size_t)r * ldb + c * 8;
        uint32_t bd = base + 2u * TILE_B + (uint32_t)(r * 80 + c * 16);
        CP16(bd, bs); CP16(bd + TILE_B, bs + bLO);
    }
}

__device__ __forceinline__ void compute_stage(uint32_t stage_base, uint32_t aoff, uint32_t boff,
                                              float acc[4][4][4]) {
#pragma unroll
    for (int kk = 0; kk < 2; ++kk) {
        uint32_t ah[4][4], al[4][4];
        uint32_t ab = stage_base + aoff + kk * 32u;
#pragma unroll
        for (int i = 0; i < 4; ++i) {
            ldm4(ah[i], ab + (uint32_t)i * 1280u);
            ldm4(al[i], ab + (uint32_t)TILE_B + (uint32_t)i * 1280u);
        }
        uint32_t bb = stage_base + 2u * TILE_B + boff + kk * 32u;
#pragma unroll
        for (int s2 = 0; s2 < 2; ++s2) {
            uint32_t th[4], tl[4];
            ldm4(th, bb + (uint32_t)s2 * 1280u);
            ldm4(tl, bb + (uint32_t)TILE_B + (uint32_t)s2 * 1280u);
            uint32_t b0[2] = { th[0], th[1] }, b1[2] = { th[2], th[3] };
            uint32_t c0[2] = { tl[0], tl[1] }, c1[2] = { tl[2], tl[3] };
#pragma unroll
            for (int i = 0; i < 4; ++i) {
                mma_bf16(acc[i][2 * s2],     ah[i], b0);
                mma_bf16(acc[i][2 * s2],     ah[i], c0);
                mma_bf16(acc[i][2 * s2],     al[i], b0);
                mma_bf16(acc[i][2 * s2 + 1], ah[i], b1);
                mma_bf16(acc[i][2 * s2 + 1], ah[i], c1);
                mma_bf16(acc[i][2 * s2 + 1], al[i], b1);
            }
        }
    }
}

template <int NIT, typename AF, typename BF>
__device__ __forceinline__ void gemm_run2(char* smem, int tid, AF af, size_t lda, size_t aLO,
                                          BF bf, size_t ldb, size_t bLO, float acc[4][4][4]) {
    const int lane = tid & 31, wid = tid >> 5;
    const int wm = (wid >> 2) * 64, wn = (wid & 3) * 32;
    const uint32_t aoff = (uint32_t)((wm + (lane & 7) + ((lane >> 3) & 1) * 8) * 80 + (lane >> 4) * 16);
    const uint32_t boff = (uint32_t)((wn + (lane & 7) + (lane >> 4) * 8) * 80 + ((lane >> 3) & 1) * 16);
    const uint32_t sb = smem_u32(smem);

#pragma unroll
    for (int i = 0; i < 4; ++i)
#pragma unroll
        for (int j = 0; j < 4; ++j)
#pragma unroll
            for (int e = 0; e < 4; ++e) acc[i][j][e] = 0.0f;

    cpa_ab(sb, 0, af(0), lda, aLO, bf(0), ldb, bLO, tid);
    CP_COMMIT(); CP_WAIT0(); __syncthreads();

    for (int it = 0; it < NIT; ++it) {
        int cur = it & 1;
        if (it + 1 < NIT) {
            cpa_ab(sb, cur ^ 1, af(it + 1), lda, aLO, bf(it + 1), ldb, bLO, tid);
            CP_COMMIT();
        }
        compute_stage(sb + (uint32_t)cur * STAGE_B, aoff, boff, acc);
        CP_WAIT0(); __syncthreads();
    }
}

// ---------------------------------------------------------------------------
// Prep: x -> bf16 hi/lo
// ---------------------------------------------------------------------------
__global__ __launch_bounds__(256)
void prep_x(const float* __restrict__ x) {
    size_t i = ((size_t)blockIdx.x * 256 + threadIdx.x) * 4;
    float4 v = *(const float4*)(x + i);
    uint32_t h0, l0, h1, l1;
    split2(v.x, v.y, h0, l0);
    split2(v.z, v.w, h1, l1);
    *(uint32_t*)(&g_x2[0][i])     = h0; *(uint32_t*)(&g_x2[0][i + 2]) = h1;
    *(uint32_t*)(&g_x2[1][i])     = l0; *(uint32_t*)(&g_x2[1][i + 2]) = l1;
}

// ---------------------------------------------------------------------------
// Weight transpose + split
// ---------------------------------------------------------------------------
__global__ __launch_bounds__(256)
void transpose_w(const float* __restrict__ wq, const float* __restrict__ wk,
                 const float* __restrict__ wv, const float* __restrict__ wo) {
    int z = blockIdx.z;
    const float* src = (z == 0) ? wq : (z == 1) ? wk : (z == 2) ? wv : wo;
    __shared__ float t[32][33];
    int x0 = blockIdx.x * 32, y0 = blockIdx.y * 32;
    int tx = threadIdx.x, ty = threadIdx.y;
#pragma unroll
    for (int j = 0; j < 32; j += 8)
        t[ty + j][tx] = src[(size_t)(y0 + ty + j) * H_ + x0 + tx];
    __syncthreads();
#pragma unroll
    for (int j = 0; j < 32; j += 8) {
        __nv_bfloat16 h, l;
        split1(t[tx][ty + j], h, l);
        size_t o = (size_t)(x0 + ty + j) * H_ + y0 + tx;
        g_wt2[z][0][o] = h;
        g_wt2[z][1][o] = l;
    }
}

// ---------------------------------------------------------------------------
// Kernel 1: QKV projections (EXACT R8). grid (16, 32, 3).
// ---------------------------------------------------------------------------
__global__ __launch_bounds__(256)
void qkv_mma(const float* __restrict__ bq, const float* __restrict__ bk,
             const float* __restrict__ bv) {
    extern __shared__ char smem[];
    const int tid = threadIdx.x, lane = tid & 31, wid = tid >> 5;
    const int wm = (wid >> 2) * 64, wn = (wid & 3) * 32;
    const int z = blockIdx.z, h = blockIdx.x, m0 = blockIdx.y * 128, n0 = h * 128;
    const float* bias = (z == 0) ? bq : (z == 1) ? bk : bv;

    float acc[4][4][4];
    gemm_run2<64>(smem, tid,
        [&](int it) { return &g_x2[0][(size_t)m0 * H_ + it * 32]; }, (size_t)H_, (size_t)M_ * H_,
        [&](int it) { return &g_wt2[z][0][(size_t)n0 * H_ + it * 32]; }, (size_t)H_, (size_t)H_ * H_,
        acc);

    const int bb = m0 >> 11, s0 = m0 & (S_ - 1);
    if (z < 2) {
        __nv_bfloat16* base = ((z == 0) ? g_q2[0] : g_k2[0]) + (size_t)(bb * NH_ + h) * S_ * HD_;
#pragma unroll
        for (int i = 0; i < 4; ++i)
#pragma unroll
            for (int j = 0; j < 4; ++j)
#pragma unroll
                for (int hf = 0; hf < 2; ++hf) {
                    int s = s0 + wm + i * 16 + (lane >> 2) + hf * 8;
                    int d = wn + j * 8 + ((lane & 3) << 1);
                    uint32_t hh, ll;
                    split2(acc[i][j][hf * 2] + bias[n0 + d],
                           acc[i][j][hf * 2 + 1] + bias[n0 + d + 1], hh, ll);
                    *(uint32_t*)(base + (size_t)s * HD_ + d)            = hh;
                    *(uint32_t*)(base + LO_QKVA + (size_t)s * HD_ + d)  = ll;
                }
    } else {
        __nv_bfloat16* vb = g_vT2[0] + (size_t)(bb * NH_ + h) * HD_ * S_;
#pragma unroll
        for (int i = 0; i < 4; ++i)
#pragma unroll
            for (int j = 0; j < 4; ++j)
#pragma unroll
                for (int hf = 0; hf < 2; ++hf) {
                    int s = s0 + wm + i * 16 + (lane >> 2) + hf * 8;
                    int d = wn + j * 8 + ((lane & 3) << 1);
                    __nv_bfloat16 h0, l0, h1, l1;
                    split1(acc[i][j][hf * 2] + bias[n0 + d], h0, l0);
                    split1(acc[i][j][hf * 2 + 1] + bias[n0 + d + 1], h1, l1);
                    vb[(size_t)d * S_ + s]                 = h0;
                    vb[LO_QKVA + (size_t)d * S_ + s]       = l0;
                    vb[(size_t)(d + 1) * S_ + s]           = h1;
                    vb[LO_QKVA + (size_t)(d + 1) * S_ + s] = l1;
                }
    }
}

// ---------------------------------------------------------------------------
// Flash attention, skewed-softmax pipeline:
//   iter kb: S(kb) -> [softmax(kb) (no acc) || PV(kb-1)] -> acc*=f(kb)
// K loads committed at iter top; V loads after mid-sync. No barrier inside
// the softmax/PV region so ptxas can interleave scalar and tensor work.
// ---------------------------------------------------------------------------
static constexpr int QPL  = 128 * 272;
static constexpr int KPL  = 64 * 272;
static constexpr int VPL  = 128 * 144;
static constexpr int FSTG = 2 * KPL + 2 * VPL;
static constexpr int SOFF = 2 * QPL;
static constexpr int SMEM_F = SOFF + 2 * FSTG;    // 212992

__device__ __forceinline__ void load_k(uint32_t stg, const __nv_bfloat16* Kh, int s0, int tid) {
#pragma unroll
    for (int i = 0; i < 4; ++i) {
        int idx = tid + (i << 8);
        int r = idx >> 4, c = idx & 15;
        const __nv_bfloat16* s = Kh + (size_t)(s0 + r) * HD_ + c * 8;
        uint32_t d = stg + (uint32_t)(r * 272 + c * 16);
        CP16(d, s); CP16(d + KPL, s + LO_QKVA);
    }
}
__device__ __forceinline__ void load_v(uint32_t stg, const __nv_bfloat16* Vh, int s0, int tid) {
#pragma unroll
    for (int i = 0; i < 4; ++i) {
        int idx = tid + (i << 8);
        int r = idx >> 3, c = idx & 7;
        const __nv_bfloat16* s = Vh + (size_t)r * S_ + s0 + c * 8;
        uint32_t d = stg + 2u * KPL + (uint32_t)(r * 144 + c * 16);
        CP16(d, s); CP16(d + VPL, s + LO_QKVA);
    }
}

// S = Q K^T (3-term split). Q-hi in regs; Q-lo reloaded per kk from smem.
__device__ __forceinline__ void s_phase(uint32_t stg, uint32_t koff, uint32_t qlo_base,
                                        const uint32_t aqh[8][4], float ps[8][4]) {
#pragma unroll
    for (int j = 0; j < 8; ++j) { ps[j][0] = ps[j][1] = ps[j][2] = ps[j][3] = 0.0f; }
    uint32_t ka = stg + koff;
#pragma unroll
    for (int kk = 0; kk < 8; ++kk) {
        uint32_t aql[4];
        ldm4(aql, qlo_base + (uint32_t)kk * 32);
#pragma unroll
        for (int s2 = 0; s2 < 4; ++s2) {
            uint32_t th[4], tl[4];
            ldm4(th, ka + (uint32_t)(s2 * 16 * 272) + (uint32_t)kk * 32);
            ldm4(tl, ka + KPL + (uint32_t)(s2 * 16 * 272) + (uint32_t)kk * 32);
            uint32_t b0[2] = { th[0], th[1] }, b1[2] = { th[2], th[3] };
            uint32_t c0[2] = { tl[0], tl[1] }, c1[2] = { tl[2], tl[3] };
            mma_bf16(ps[2 * s2],     aqh[kk], b0);
            mma_bf16(ps[2 * s2],     aqh[kk], c0);
            mma_bf16(ps[2 * s2],     aql,     b0);
            mma_bf16(ps[2 * s2 + 1], aqh[kk], b1);
            mma_bf16(ps[2 * s2 + 1], aqh[kk], c1);
            mma_bf16(ps[2 * s2 + 1], aql,     b1);
        }
    }
}

// O += P V ; P split on the fly from fp32 ps regs.
__device__ __forceinline__ void pv_phase(uint32_t va, const float pc[8][4], float acc_o[16][4]) {
#pragma unroll
    for (int kk2 = 0; kk2 < 4; ++kk2) {
        uint32_t pah[4], pal[4];
        split2(pc[2 * kk2][0],     pc[2 * kk2][1],     pah[0], pal[0]);
        split2(pc[2 * kk2][2],     pc[2 * kk2][3],     pah[1], pal[1]);
        split2(pc[2 * kk2 + 1][0], pc[2 * kk2 + 1][1], pah[2], pal[2]);
        split2(pc[2 * kk2 + 1][2], pc[2 * kk2 + 1][3], pah[3], pal[3]);
#pragma unroll
        for (int s2 = 0; s2 < 8; ++s2) {
            uint32_t th[4], tl[4];
            ldm4(th, va + (uint32_t)(s2 * 16 * 144) + (uint32_t)kk2 * 32);
            ldm4(tl, va + VPL + (uint32_t)(s2 * 16 * 144) + (uint32_t)kk2 * 32);
            uint32_t b0[2] = { th[0], th[1] }, b1[2] = { th[2], th[3] };
            uint32_t c0[2] = { tl[0], tl[1] }, c1[2] = { tl[2], tl[3] };
            mma_bf16(acc_o[2 * s2],     pah, b0);
            mma_bf16(acc_o[2 * s2],     pah, c0);
            mma_bf16(acc_o[2 * s2],     pal, b0);
            mma_bf16(acc_o[2 * s2 + 1], pah, b1);
            mma_bf16(acc_o[2 * s2 + 1], pah, c1);
            mma_bf16(acc_o[2 * s2 + 1], pal, b1);
        }
    }
}

__global__ __launch_bounds__(256)
void flash_attn(const float* __restrict__ mask) {
    extern __shared__ char smem[];
    const int tid = threadIdx.x, lane = tid & 31, wid = tid >> 5;
    const int q0 = blockIdx.x * 128, z = blockIdx.y, bb = z >> 4;
    const uint32_t sb = smem_u32(smem);
    const __nv_bfloat16* Qh = g_q2[0] + (size_t)z * S_ * HD_;
    const __nv_bfloat16* Kh = g_k2[0] + (size_t)z * S_ * HD_;
    const __nv_bfloat16* Vh = g_vT2[0] + (size_t)z * HD_ * S_;

    // Prologue: Q tile (hi+lo) + stage0 K/V in one group; drain fully.
#pragma unroll
    for (int i = 0; i < 8; ++i) {
        int idx = tid + (i << 8), r = idx >> 4, c = idx & 15;
        const __nv_bfloat16* s = Qh + (size_t)(q0 + r) * HD_ + c * 8;
        uint32_t d = sb + (uint32_t)(r * 272 + c * 16);
        CP16(d, s); CP16(d + QPL, s + LO_QKVA);
    }
    load_k(sb + SOFF, Kh, 0, tid);
    load_v(sb + SOFF, Vh, 0, tid);
    CP_COMMIT(); CP_WAIT0(); __syncthreads();

    const uint32_t qb = sb + (uint32_t)((wid * 16 + (lane & 15)) * 272 + (lane >> 4) * 16);
    const uint32_t qlo_base = qb + (uint32_t)QPL;
    uint32_t aqh[8][4];
#pragma unroll
    for (int kk = 0; kk < 8; ++kk) ldm4(aqh[kk], qb + (uint32_t)kk * 32);

    float acc_o[16][4];
#pragma unroll
    for (int j = 0; j < 16; ++j)
#pragma unroll
        for (int e = 0; e < 4; ++e) acc_o[j][e] = 0.0f;
    float l0 = 0.0f, l1 = 0.0f, m0p = -1e30f, m1p = -1e30f;
    const float SC = 0.08838834764831845f;

    const int qr = q0 + wid * 16 + (lane >> 2);
    const float* mrow = mask + ((size_t)bb * S_ + qr) * S_ + ((lane & 3) << 1);

    const uint32_t koff = (uint32_t)(((lane & 7) + ((lane >> 4) << 3)) * 272 + ((lane >> 3) & 1) * 16);
    const uint32_t voff = (uint32_t)(((lane & 7) + ((lane >> 4) << 3)) * 144 + ((lane >> 3) & 1) * 16);

    float ps[2][8][4];

    for (int kb = 0; kb < 32; ++kb) {
        const int cur = kb & 1;

        // K(kb+1) load at iter top (its slot's K was last read one iter ago).
        if (kb < 31) { load_k(sb + SOFF + (uint32_t)(cur ^ 1) * FSTG, Kh, (kb + 1) * 64, tid); CP_COMMIT(); }
        // K(kb) and V(kb-1) resident; allow newest 2 groups (V(kb), K(kb+1)) to pend.
        if (kb == 31) CP_WAIT1(); else CP_WAIT2();
        __syncthreads();

        // ---- S(kb) ----
        s_phase(sb + SOFF + (uint32_t)cur * FSTG, koff, qlo_base, aqh, ps[cur]);

        // ---- barrier-free region: softmax(kb) [no acc_o] || PV(kb-1) ----
        float (*pc)[4] = ps[cur];
        float mk0[8][2], mk1[8][2];
        {
            const float* mp = mrow + kb * 64;
#pragma unroll
            for (int j = 0; j < 8; ++j) {
                float2 u = *(const float2*)(mp + j * 8);
                float2 v = *(const float2*)(mp + 8 * (size_t)S_ + j * 8);
                mk0[j][0] = u.x; mk0[j][1] = u.y;
                mk1[j][0] = v.x; mk1[j][1] = v.y;
            }
        }
        float mx0 = -1e30f, mx1 = -1e30f;
#pragma unroll
        for (int j = 0; j < 8; ++j) {
            pc[j][0] = pc[j][0] * SC + mk0[j][0];
            pc[j][1] = pc[j][1] * SC + mk0[j][1];
            pc[j][2] = pc[j][2] * SC + mk1[j][0];
            pc[j][3] = pc[j][3] * SC + mk1[j][1];
            mx0 = fmaxf(mx0, fmaxf(pc[j][0], pc[j][1]));
            mx1 = fmaxf(mx1, fmaxf(pc[j][2], pc[j][3]));
        }
        mx0 = fmaxf(mx0, __shfl_xor_sync(0xffffffffu, mx0, 1));
        mx0 = fmaxf(mx0, __shfl_xor_sync(0xffffffffu, mx0, 2));
        mx1 = fmaxf(mx1, __shfl_xor_sync(0xffffffffu, mx1, 1));
        mx1 = fmaxf(mx1, __shfl_xor_sync(0xffffffffu, mx1, 2));
        float mn0 = fmaxf(m0p, mx0), mn1 = fmaxf(m1p, mx1);
        float f0 = __expf(m0p - mn0), f1 = __expf(m1p - mn1);
        float sa0 = 0.0f, sa1 = 0.0f;
#pragma unroll
        for (int j = 0; j < 8; ++j) {
            pc[j][0] = __expf(pc[j][0] - mn0); sa0 += pc[j][0];
            pc[j][1] = __expf(pc[j][1] - mn0); sa0 += pc[j][1];
            pc[j][2] = __expf(pc[j][2] - mn1); sa1 += pc[j][2];
            pc[j][3] = __expf(pc[j][3] - mn1); sa1 += pc[j][3];
        }
        sa0 += __shfl_xor_sync(0xffffffffu, sa0, 1);
        sa0 += __shfl_xor_sync(0xffffffffu, sa0, 2);
        sa1 += __shfl_xor_sync(0xffffffffu, sa1, 1);
        sa1 += __shfl_xor_sync(0xffffffffu, sa1, 2);
        l0 = l0 * f0 + sa0; l1 = l1 * f1 + sa1;
        m0p = mn0; m1p = mn1;

        // PV(kb-1): uses acc_o at pre-f(kb) scale and ps[cur^1] — independent of softmax above.
        if (kb > 0)
            pv_phase(sb + SOFF + (uint32_t)(cur ^ 1) * FSTG + 2u * KPL + voff, ps[cur ^ 1], acc_o);

        // Rescale AFTER PV(kb-1): O_new = O_old*f(kb); PV(kb) adds next iter.
#pragma unroll
        for (int j = 0; j < 16; ++j) {
            acc_o[j][0] *= f0; acc_o[j][1] *= f0;
            acc_o[j][2] *= f1; acc_o[j][3] *= f1;
        }

        // V(kb+1) load: its slot's V(kb-1) was just consumed by PV(kb-1) above.
        __syncthreads();
        if (kb < 31) { load_v(sb + SOFF + (uint32_t)(cur ^ 1) * FSTG, Vh, (kb + 1) * 64, tid); CP_COMMIT(); }
    }

    // Tail: PV(31) from slot 1 (V(31) committed at kb=30; drain).
    CP_WAIT0(); __syncthreads();
    pv_phase(sb + SOFF + (uint32_t)1 * FSTG + 2u * KPL + voff, ps[1], acc_o);

    // ---- epilogue ----
    float i0 = 1.0f / l0, i1 = 1.0f / l1;
    __nv_bfloat16* Ah = g_at2[0] + (size_t)z * S_ * HD_;
    int sr = q0 + wid * 16 + (lane >> 2);
#pragma unroll
    for (int j2 = 0; j2 < 16; ++j2) {
        int d = j2 * 8 + ((lane & 3) << 1);
        uint32_t hh, ll;
        split2(acc_o[j2][0] * i0, acc_o[j2][1] * i0, hh, ll);
        *(uint32_t*)(Ah + (size_t)sr * HD_ + d)           = hh;
        *(uint32_t*)(Ah + LO_QKVA + (size_t)sr * HD_ + d) = ll;
        split2(acc_o[j2][2] * i1, acc_o[j2][3] * i1, hh, ll);
        *(uint32_t*)(Ah + (size_t)(sr + 8) * HD_ + d)           = hh;
        *(uint32_t*)(Ah + LO_QKVA + (size_t)(sr + 8) * HD_ + d) = ll;
    }
}

// ---------------------------------------------------------------------------
// Kernel 3: out = gather(attn) @ W_O + b_O (EXACT R8).  grid (16, 32)
// ---------------------------------------------------------------------------
__global__ __launch_bounds__(256)
void out_mma(const float* __restrict__ bo, float* __restrict__ out) {
    extern __shared__ char smem[];
    const int tid = threadIdx.x, lane = tid & 31, wid = tid >> 5;
    const int wm = (wid >> 2) * 64, wn = (wid & 3) * 32;
    const int n0 = blockIdx.x * 128, m0 = blockIdx.y * 128;
    const int bb = m0 >> 11, s0 = m0 & (S_ - 1);

    float acc[4][4][4];
    gemm_run2<64>(smem, tid,
        [&](int it) {
            int h = it >> 2, dbase = (it & 3) * 32;
            return &g_at2[0][((size_t)(bb * NH_ + h) * S_ + s0) * HD_ + dbase];
        }, (size_t)HD_, LO_QKVA,
        [&](int it) { return &g_wt2[3][0][(size_t)n0 * H_ + it * 32]; }, (size_t)H_, (size_t)H_ * H_,
        acc);

#pragma unroll
    for (int i = 0; i < 4; ++i)
#pragma unroll
        for (int j = 0; j < 4; ++j)
#pragma unroll
            for (int hf = 0; hf < 2; ++hf) {
                int m = m0 + wm + i * 16 + (lane >> 2) + hf * 8;
                int n = n0 + wn + j * 8 + ((lane & 3) << 1);
                float2 v = make_float2(acc[i][j][hf * 2] + bo[n],
                                       acc[i][j][hf * 2 + 1] + bo[n + 1]);
                *(float2*)(out + (size_t)m * H_ + n) = v;
            }
}

// ---------------------------------------------------------------------------
// Launch
// ---------------------------------------------------------------------------
extern "C" void kernel_launch(void* const* d_in, const int* in_sizes, int n_in,
                              void* d_out, int out_size) {
    const float* batch = (const float*)d_in[0];
    const float* mask  = (const float*)d_in[1];
    const float* wq = (const float*)d_in[2]; const float* bq = (const float*)d_in[3];
    const float* wk = (const float*)d_in[4]; const float* bk = (const float*)d_in[5];
    const float* wv = (const float*)d_in[6]; const float* bv = (const float*)d_in[7];
    const float* wo = (const float*)d_in[8]; const float* bo = (const float*)d_in[9];
    float* out = (float*)d_out;

    cudaFuncSetAttribute(qkv_mma,    cudaFuncAttributeMaxDynamicSharedMemorySize, SMEM_G);
    cudaFuncSetAttribute(flash_attn, cudaFuncAttributeMaxDynamicSharedMemorySize, SMEM_F);
    cudaFuncSetAttribute(out_mma,    cudaFuncAttributeMaxDynamicSharedMemorySize, SMEM_G);

    int prep_blocks = (int)(((size_t)M_ * H_ / 4 + 255) / 256);
    prep_x<<<prep_blocks, 256>>>(batch);
    transpose_w<<<dim3(64, 64, 4), dim3(32, 8)>>>(wq, wk, wv, wo);
    qkv_mma<<<dim3(16, 32, 3), 256, SMEM_G>>>(bq, bk, bv);
    flash_attn<<<dim3(16, 32), 256, SMEM_F>>>(mask);
    out_mma<<<dim3(16, 32), 256, SMEM_G>>>(bo, out);
}

// round 17
// speedup vs baseline: 1.1793x; 1.0641x over previous
#include <cuda_runtime.h>
#include <cuda_bf16.h>
#include <cstdint>

#define B_   2
#define S_   2048
#define H_   2048
#define NH_  16
#define HD_  128
#define M_   (B_ * S_)
#define BH_  (B_ * NH_)

// ---------------------------------------------------------------------------
// Device-global scratch (hi plane at [0], lo plane at [1])
// ---------------------------------------------------------------------------
__device__ __nv_bfloat16 g_wt2[4][2][(size_t)H_ * H_];     // WT[n][k], split
__device__ __nv_bfloat16 g_x2[2][(size_t)M_ * H_];         // batch, split
__device__ __nv_bfloat16 g_q2[2][(size_t)BH_ * S_ * HD_];  // [b,h,s,d]  (Q pre-scaled by SC*log2e)
__device__ __nv_bfloat16 g_k2[2][(size_t)BH_ * S_ * HD_];  // [b,h,s,d]
__device__ __nv_bfloat16 g_vT2[2][(size_t)BH_ * HD_ * S_]; // [b,h,d,s]
__device__ __nv_bfloat16 g_at2[2][(size_t)BH_ * S_ * HD_]; // [b,h,s,d]

static constexpr size_t LO_QKVA = (size_t)BH_ * S_ * HD_;  // plane stride (elems)
static constexpr float LOG2E = 1.4426950408889634f;
static constexpr float SCL2E = 0.08838834764831845f * 1.4426950408889634f;  // (1/sqrt(128))*log2e

// ---------------------------------------------------------------------------
// PTX helpers
// ---------------------------------------------------------------------------
__device__ __forceinline__ uint32_t smem_u32(const void* p) {
    uint32_t a;
    asm("{ .reg .u64 t; cvta.to.shared.u64 t, %1; cvt.u32.u64 %0, t; }" : "=r"(a) : "l"(p));
    return a;
}

__device__ __forceinline__ void ldm4(uint32_t* r, uint32_t addr) {
    asm volatile("ldmatrix.sync.aligned.m8n8.x4.shared.b16 {%0,%1,%2,%3}, [%4];"
        : "=r"(r[0]), "=r"(r[1]), "=r"(r[2]), "=r"(r[3]) : "r"(addr));
}

__device__ __forceinline__ void mma_bf16(float* c, const uint32_t* a, const uint32_t* b) {
    asm volatile(
        "mma.sync.aligned.m16n8k16.row.col.f32.bf16.bf16.f32 "
        "{%0,%1,%2,%3}, {%4,%5,%6,%7}, {%8,%9}, {%0,%1,%2,%3};"
        : "+f"(c[0]), "+f"(c[1]), "+f"(c[2]), "+f"(c[3])
        : "r"(a[0]), "r"(a[1]), "r"(a[2]), "r"(a[3]), "r"(b[0]), "r"(b[1]));
}

__device__ __forceinline__ float ex2f(float x) {
    float r;
    asm("ex2.approx.f32 %0, %1;" : "=f"(r) : "f"(x));
    return r;
}

#define CP16(dst, src)  asm volatile("cp.async.cg.shared.global [%0], [%1], 16;" :: "r"(dst), "l"(src))
#define CP_COMMIT()     asm volatile("cp.async.commit_group;" ::: "memory")
#define CP_WAIT0()      asm volatile("cp.async.wait_group 0;" ::: "memory")

// fp32 -> bf16 hi + bf16 lo (packed pair)
__device__ __forceinline__ void split2(float a, float b, uint32_t& hi, uint32_t& lo) {
    __nv_bfloat162 h = __floats2bfloat162_rn(a, b);
    __nv_bfloat162 l = __floats2bfloat162_rn(a - __bfloat162float(h.x), b - __bfloat162float(h.y));
    hi = *reinterpret_cast<uint32_t*>(&h);
    lo = *reinterpret_cast<uint32_t*>(&l);
}
__device__ __forceinline__ void split1(float v, __nv_bfloat16& h, __nv_bfloat16& l) {
    h = __float2bfloat16_rn(v);
    l = __float2bfloat16_rn(v - __bfloat162float(h));
}

// ---------------------------------------------------------------------------
// GEMM core (qkv/out): EXACT R8 config. 128x128 tile, BK=32 bf16 hi/lo,
// cp.async double buffer, SMEM 81920 -> 2 CTAs/SM naturally.
// ---------------------------------------------------------------------------
static constexpr int TILE_B  = 10240;
static constexpr int STAGE_B = 4 * TILE_B;
static constexpr int SMEM_G  = 2 * STAGE_B;   // 81920

__device__ __forceinline__ void cpa_ab(uint32_t sb, int stage,
                                       const __nv_bfloat16* asrc, size_t lda, size_t aLO,
                                       const __nv_bfloat16* bsrc, size_t ldb, size_t bLO, int tid) {
    uint32_t base = sb + (uint32_t)stage * STAGE_B;
#pragma unroll
    for (int i = 0; i < 2; ++i) {
        int idx = tid + (i << 8), r = idx >> 2, c = idx & 3;
        const __nv_bfloat16* as = asrc + (size_t)r * lda + c * 8;
        uint32_t ad = base + (uint32_t)(r * 80 + c * 16);
        CP16(ad, as); CP16(ad + TILE_B, as + aLO);
        const __nv_bfloat16* bs = bsrc + (size_t)r * ldb + c * 8;
        uint32_t bd = base + 2u * TILE_B + (uint32_t)(r * 80 + c * 16);
        CP16(bd, bs); CP16(bd + TILE_B, bs + bLO);
    }
}

__device__ __forceinline__ void compute_stage(uint32_t stage_base, uint32_t aoff, uint32_t boff,
                                              float acc[4][4][4]) {
#pragma unroll
    for (int kk = 0; kk < 2; ++kk) {
        uint32_t ah[4][4], al[4][4];
        uint32_t ab = stage_base + aoff + kk * 32u;
#pragma unroll
        for (int i = 0; i < 4; ++i) {
            ldm4(ah[i], ab + (uint32_t)i * 1280u);
            ldm4(al[i], ab + (uint32_t)TILE_B + (uint32_t)i * 1280u);
        }
        uint32_t bb = stage_base + 2u * TILE_B + boff + kk * 32u;
#pragma unroll
        for (int s2 = 0; s2 < 2; ++s2) {
            uint32_t th[4], tl[4];
            ldm4(th, bb + (uint32_t)s2 * 1280u);
            ldm4(tl, bb + (uint32_t)TILE_B + (uint32_t)s2 * 1280u);
            uint32_t b0[2] = { th[0], th[1] }, b1[2] = { th[2], th[3] };
            uint32_t c0[2] = { tl[0], tl[1] }, c1[2] = { tl[2], tl[3] };
#pragma unroll
            for (int i = 0; i < 4; ++i) {
                mma_bf16(acc[i][2 * s2],     ah[i], b0);
                mma_bf16(acc[i][2 * s2],     ah[i], c0);
                mma_bf16(acc[i][2 * s2],     al[i], b0);
                mma_bf16(acc[i][2 * s2 + 1], ah[i], b1);
                mma_bf16(acc[i][2 * s2 + 1], ah[i], c1);
                mma_bf16(acc[i][2 * s2 + 1], al[i], b1);
            }
        }
    }
}

template <int NIT, typename AF, typename BF>
__device__ __forceinline__ void gemm_run2(char* smem, int tid, AF af, size_t lda, size_t aLO,
                                          BF bf, size_t ldb, size_t bLO, float acc[4][4][4]) {
    const int lane = tid & 31, wid = tid >> 5;
    const int wm = (wid >> 2) * 64, wn = (wid & 3) * 32;
    const uint32_t aoff = (uint32_t)((wm + (lane & 7) + ((lane >> 3) & 1) * 8) * 80 + (lane >> 4) * 16);
    const uint32_t boff = (uint32_t)((wn + (lane & 7) + (lane >> 4) * 8) * 80 + ((lane >> 3) & 1) * 16);
    const uint32_t sb = smem_u32(smem);

#pragma unroll
    for (int i = 0; i < 4; ++i)
#pragma unroll
        for (int j = 0; j < 4; ++j)
#pragma unroll
            for (int e = 0; e < 4; ++e) acc[i][j][e] = 0.0f;

    cpa_ab(sb, 0, af(0), lda, aLO, bf(0), ldb, bLO, tid);
    CP_COMMIT(); CP_WAIT0(); __syncthreads();

    for (int it = 0; it < NIT; ++it) {
        int cur = it & 1;
        if (it + 1 < NIT) {
            cpa_ab(sb, cur ^ 1, af(it + 1), lda, aLO, bf(it + 1), ldb, bLO, tid);
            CP_COMMIT();
        }
        compute_stage(sb + (uint32_t)cur * STAGE_B, aoff, boff, acc);
        CP_WAIT0(); __syncthreads();
    }
}

// ---------------------------------------------------------------------------
// Prep: x -> bf16 hi/lo
// ---------------------------------------------------------------------------
__global__ __launch_bounds__(256)
void prep_x(const float* __restrict__ x) {
    size_t i = ((size_t)blockIdx.x * 256 + threadIdx.x) * 4;
    float4 v = *(const float4*)(x + i);
    uint32_t h0, l0, h1, l1;
    split2(v.x, v.y, h0, l0);
    split2(v.z, v.w, h1, l1);
    *(uint32_t*)(&g_x2[0][i])     = h0; *(uint32_t*)(&g_x2[0][i + 2]) = h1;
    *(uint32_t*)(&g_x2[1][i])     = l0; *(uint32_t*)(&g_x2[1][i + 2]) = l1;
}

// ---------------------------------------------------------------------------
// Weight transpose + split
// ---------------------------------------------------------------------------
__global__ __launch_bounds__(256)
void transpose_w(const float* __restrict__ wq, const float* __restrict__ wk,
                 const float* __restrict__ wv, const float* __restrict__ wo) {
    int z = blockIdx.z;
    const float* src = (z == 0) ? wq : (z == 1) ? wk : (z == 2) ? wv : wo;
    __shared__ float t[32][33];
    int x0 = blockIdx.x * 32, y0 = blockIdx.y * 32;
    int tx = threadIdx.x, ty = threadIdx.y;
#pragma unroll
    for (int j = 0; j < 32; j += 8)
        t[ty + j][tx] = src[(size_t)(y0 + ty + j) * H_ + x0 + tx];
    __syncthreads();
#pragma unroll
    for (int j = 0; j < 32; j += 8) {
        __nv_bfloat16 h, l;
        split1(t[tx][ty + j], h, l);
        size_t o = (size_t)(x0 + ty + j) * H_ + y0 + tx;
        g_wt2[z][0][o] = h;
        g_wt2[z][1][o] = l;
    }
}

// ---------------------------------------------------------------------------
// Kernel 1: QKV projections (EXACT R8 structure). grid (16, 32, 3).
// Q is pre-scaled by SC*log2e in the epilogue (folds softmax scale into GEMM).
// ---------------------------------------------------------------------------
__global__ __launch_bounds__(256)
void qkv_mma(const float* __restrict__ bq, const float* __restrict__ bk,
             const float* __restrict__ bv) {
    extern __shared__ char smem[];
    const int tid = threadIdx.x, lane = tid & 31, wid = tid >> 5;
    const int wm = (wid >> 2) * 64, wn = (wid & 3) * 32;
    const int z = blockIdx.z, h = blockIdx.x, m0 = blockIdx.y * 128, n0 = h * 128;
    const float* bias = (z == 0) ? bq : (z == 1) ? bk : bv;

    float acc[4][4][4];
    gemm_run2<64>(smem, tid,
        [&](int it) { return &g_x2[0][(size_t)m0 * H_ + it * 32]; }, (size_t)H_, (size_t)M_ * H_,
        [&](int it) { return &g_wt2[z][0][(size_t)n0 * H_ + it * 32]; }, (size_t)H_, (size_t)H_ * H_,
        acc);

    const int bb = m0 >> 11, s0 = m0 & (S_ - 1);
    if (z < 2) {
        const float scl = (z == 0) ? SCL2E : 1.0f;   // Q pre-scaled for base-2 softmax
        __nv_bfloat16* base = ((z == 0) ? g_q2[0] : g_k2[0]) + (size_t)(bb * NH_ + h) * S_ * HD_;
#pragma unroll
        for (int i = 0; i < 4; ++i)
#pragma unroll
            for (int j = 0; j < 4; ++j)
#pragma unroll
                for (int hf = 0; hf < 2; ++hf) {
                    int s = s0 + wm + i * 16 + (lane >> 2) + hf * 8;
                    int d = wn + j * 8 + ((lane & 3) << 1);
                    uint32_t hh, ll;
                    split2((acc[i][j][hf * 2] + bias[n0 + d]) * scl,
                           (acc[i][j][hf * 2 + 1] + bias[n0 + d + 1]) * scl, hh, ll);
                    *(uint32_t*)(base + (size_t)s * HD_ + d)            = hh;
                    *(uint32_t*)(base + LO_QKVA + (size_t)s * HD_ + d)  = ll;
                }
    } else {
        __nv_bfloat16* vb = g_vT2[0] + (size_t)(bb * NH_ + h) * HD_ * S_;
#pragma unroll
        for (int i = 0; i < 4; ++i)
#pragma unroll
            for (int j = 0; j < 4; ++j)
#pragma unroll
                for (int hf = 0; hf < 2; ++hf) {
                    int s = s0 + wm + i * 16 + (lane >> 2) + hf * 8;
                    int d = wn + j * 8 + ((lane & 3) << 1);
                    __nv_bfloat16 h0, l0, h1, l1;
                    split1(acc[i][j][hf * 2] + bias[n0 + d], h0, l0);
                    split1(acc[i][j][hf * 2 + 1] + bias[n0 + d + 1], h1, l1);
                    vb[(size_t)d * S_ + s]                 = h0;
                    vb[LO_QKVA + (size_t)d * S_ + s]       = l0;
                    vb[(size_t)(d + 1) * S_ + s]           = h1;
                    vb[LO_QKVA + (size_t)(d + 1) * S_ + s] = l1;
                }
    }
}

// ---------------------------------------------------------------------------
// Flash attention: EXACT R8 structure; softmax in base-2 domain
// (Q pre-scaled by SC*log2e, mask scaled by log2e at load, ex2.approx).
// grid (16 qblocks, 32 z). K-block = 64 keys, double-buffered.
// ---------------------------------------------------------------------------
static constexpr int QPL  = 128 * 272;
static constexpr int KPL  = 64 * 272;
static constexpr int VPL  = 128 * 144;
static constexpr int FSTG = 2 * KPL + 2 * VPL;
static constexpr int SOFF = 2 * QPL;
static constexpr int SMEM_F = SOFF + 2 * FSTG;    // 212992

__device__ __forceinline__ void load_kv(uint32_t stg, const __nv_bfloat16* Kh,
                                        const __nv_bfloat16* Vh, int s0, int tid) {
#pragma unroll
    for (int i = 0; i < 4; ++i) {
        int idx = tid + (i << 8);
        {
            int r = idx >> 4, c = idx & 15;
            const __nv_bfloat16* s = Kh + (size_t)(s0 + r) * HD_ + c * 8;
            uint32_t d = stg + (uint32_t)(r * 272 + c * 16);
            CP16(d, s); CP16(d + KPL, s + LO_QKVA);
        }
        {
            int r = idx >> 3, c = idx & 7;
            const __nv_bfloat16* s = Vh + (size_t)r * S_ + s0 + c * 8;
            uint32_t d = stg + 2u * KPL + (uint32_t)(r * 144 + c * 16);
            CP16(d, s); CP16(d + VPL, s + LO_QKVA);
        }
    }
}

__global__ __launch_bounds__(256)
void flash_attn(const float* __restrict__ mask) {
    extern __shared__ char smem[];
    const int tid = threadIdx.x, lane = tid & 31, wid = tid >> 5;
    const int q0 = blockIdx.x * 128, z = blockIdx.y, bb = z >> 4;
    const uint32_t sb = smem_u32(smem);
    const __nv_bfloat16* Qh = g_q2[0] + (size_t)z * S_ * HD_;
    const __nv_bfloat16* Kh = g_k2[0] + (size_t)z * S_ * HD_;
    const __nv_bfloat16* Vh = g_vT2[0] + (size_t)z * HD_ * S_;

#pragma unroll
    for (int i = 0; i < 8; ++i) {
        int idx = tid + (i << 8), r = idx >> 4, c = idx & 15;
        const __nv_bfloat16* s = Qh + (size_t)(q0 + r) * HD_ + c * 8;
        uint32_t d = sb + (uint32_t)(r * 272 + c * 16);
        CP16(d, s); CP16(d + QPL, s + LO_QKVA);
    }
    load_kv(sb + SOFF, Kh, Vh, 0, tid);
    CP_COMMIT(); CP_WAIT0(); __syncthreads();

    uint32_t aqh[8][4], aql[8][4];
    {
        uint32_t qb = sb + (uint32_t)((wid * 16 + (lane & 15)) * 272 + (lane >> 4) * 16);
#pragma unroll
        for (int kk = 0; kk < 8; ++kk) {
            ldm4(aqh[kk], qb + (uint32_t)kk * 32);
            ldm4(aql[kk], qb + QPL + (uint32_t)kk * 32);
        }
    }

    float acc_o[16][4];
#pragma unroll
    for (int j = 0; j < 16; ++j)
#pragma unroll
        for (int e = 0; e < 4; ++e) acc_o[j][e] = 0.0f;
    float l0 = 0.0f, l1 = 0.0f, m0p = -1e30f, m1p = -1e30f;

    const int qr = q0 + wid * 16 + (lane >> 2);
    const float* mrow = mask + ((size_t)bb * S_ + qr) * S_ + ((lane & 3) << 1);

    const uint32_t koff = (uint32_t)(((lane & 7) + ((lane >> 4) << 3)) * 272 + ((lane >> 3) & 1) * 16);
    const uint32_t voff = (uint32_t)(((lane & 7) + ((lane >> 4) << 3)) * 144 + ((lane >> 3) & 1) * 16);

    for (int kb = 0; kb < 32; ++kb) {
        int cur = kb & 1;
        if (kb + 1 < 32) {
            load_kv(sb + SOFF + (uint32_t)(cur ^ 1) * FSTG, Kh, Vh, (kb + 1) * 64, tid);
            CP_COMMIT();
        }
        // mask fragments, pre-scaled to log2 domain (off critical chain)
        float mk0[8][2], mk1[8][2];
        {
            const float* mp = mrow + kb * 64;
#pragma unroll
            for (int j = 0; j < 8; ++j) {
                float2 u = *(const float2*)(mp + j * 8);
                float2 v = *(const float2*)(mp + 8 * (size_t)S_ + j * 8);
                mk0[j][0] = u.x * LOG2E; mk0[j][1] = u.y * LOG2E;
                mk1[j][0] = v.x * LOG2E; mk1[j][1] = v.y * LOG2E;
            }
        }
        uint32_t stg = sb + SOFF + (uint32_t)cur * FSTG;

        // ---- S = Q K^T (Q already carries SC*log2e) ----
        float ps[8][4];
#pragma unroll
        for (int j = 0; j < 8; ++j) { ps[j][0] = ps[j][1] = ps[j][2] = ps[j][3] = 0.0f; }
        uint32_t ka = stg + koff;
#pragma unroll
        for (int kk = 0; kk < 8; ++kk) {
#pragma unroll
            for (int s2 = 0; s2 < 4; ++s2) {
                uint32_t th[4], tl[4];
                ldm4(th, ka + (uint32_t)(s2 * 16 * 272) + (uint32_t)kk * 32);
                ldm4(tl, ka + KPL + (uint32_t)(s2 * 16 * 272) + (uint32_t)kk * 32);
                uint32_t b0[2] = { th[0], th[1] }, b1[2] = { th[2], th[3] };
                uint32_t c0[2] = { tl[0], tl[1] }, c1[2] = { tl[2], tl[3] };
                mma_bf16(ps[2 * s2],     aqh[kk], b0);
                mma_bf16(ps[2 * s2],     aqh[kk], c0);
                mma_bf16(ps[2 * s2],     aql[kk], b0);
                mma_bf16(ps[2 * s2 + 1], aqh[kk], b1);
                mma_bf16(ps[2 * s2 + 1], aqh[kk], c1);
                mma_bf16(ps[2 * s2 + 1], aql[kk], b1);
            }
        }

        // ---- online softmax in base-2 domain ----
        float mx0 = -1e30f, mx1 = -1e30f;
#pragma unroll
        for (int j = 0; j < 8; ++j) {
            ps[j][0] += mk0[j][0];
            ps[j][1] += mk0[j][1];
            ps[j][2] += mk1[j][0];
            ps[j][3] += mk1[j][1];
            mx0 = fmaxf(mx0, fmaxf(ps[j][0], ps[j][1]));
            mx1 = fmaxf(mx1, fmaxf(ps[j][2], ps[j][3]));
        }
        mx0 = fmaxf(mx0, __shfl_xor_sync(0xffffffffu, mx0, 1));
        mx0 = fmaxf(mx0, __shfl_xor_sync(0xffffffffu, mx0, 2));
        mx1 = fmaxf(mx1, __shfl_xor_sync(0xffffffffu, mx1, 1));
        mx1 = fmaxf(mx1, __shfl_xor_sync(0xffffffffu, mx1, 2));
        float mn0 = fmaxf(m0p, mx0), mn1 = fmaxf(m1p, mx1);
        float f0 = ex2f(m0p - mn0), f1 = ex2f(m1p - mn1);
        float sa0 = 0.0f, sa1 = 0.0f;
#pragma unroll
        for (int j = 0; j < 8; ++j) {
            ps[j][0] = ex2f(ps[j][0] - mn0); sa0 += ps[j][0];
            ps[j][1] = ex2f(ps[j][1] - mn0); sa0 += ps[j][1];
            ps[j][2] = ex2f(ps[j][2] - mn1); sa1 += ps[j][2];
            ps[j][3] = ex2f(ps[j][3] - mn1); sa1 += ps[j][3];
        }
        sa0 += __shfl_xor_sync(0xffffffffu, sa0, 1);
        sa0 += __shfl_xor_sync(0xffffffffu, sa0, 2);
        sa1 += __shfl_xor_sync(0xffffffffu, sa1, 1);
        sa1 += __shfl_xor_sync(0xffffffffu, sa1, 2);
        l0 = l0 * f0 + sa0; l1 = l1 * f1 + sa1;
        m0p = mn0; m1p = mn1;
#pragma unroll
        for (int j = 0; j < 16; ++j) {
            acc_o[j][0] *= f0; acc_o[j][1] *= f0;
            acc_o[j][2] *= f1; acc_o[j][3] *= f1;
        }

        // ---- O += P V ----
        uint32_t va = stg + 2u * KPL + voff;
#pragma unroll
        for (int kk2 = 0; kk2 < 4; ++kk2) {
            uint32_t pah[4], pal[4];
            split2(ps[2 * kk2][0],     ps[2 * kk2][1],     pah[0], pal[0]);
            split2(ps[2 * kk2][2],     ps[2 * kk2][3],     pah[1], pal[1]);
            split2(ps[2 * kk2 + 1][0], ps[2 * kk2 + 1][1], pah[2], pal[2]);
            split2(ps[2 * kk2 + 1][2], ps[2 * kk2 + 1][3], pah[3], pal[3]);
#pragma unroll
            for (int s2 = 0; s2 < 8; ++s2) {
                uint32_t th[4], tl[4];
                ldm4(th, va + (uint32_t)(s2 * 16 * 144) + (uint32_t)kk2 * 32);
                ldm4(tl, va + VPL + (uint32_t)(s2 * 16 * 144) + (uint32_t)kk2 * 32);
                uint32_t b0[2] = { th[0], th[1] }, b1[2] = { th[2], th[3] };
                uint32_t c0[2] = { tl[0], tl[1] }, c1[2] = { tl[2], tl[3] };
                mma_bf16(acc_o[2 * s2],     pah, b0);
                mma_bf16(acc_o[2 * s2],     pah, c0);
                mma_bf16(acc_o[2 * s2],     pal, b0);
                mma_bf16(acc_o[2 * s2 + 1], pah, b1);
                mma_bf16(acc_o[2 * s2 + 1], pah, c1);
                mma_bf16(acc_o[2 * s2 + 1], pal, b1);
            }
        }
        CP_WAIT0(); __syncthreads();
    }

    // ---- epilogue: O/l -> hi/lo bf16 ----
    float i0 = 1.0f / l0, i1 = 1.0f / l1;
    __nv_bfloat16* Ah = g_at2[0] + (size_t)z * S_ * HD_;
    int sr = q0 + wid * 16 + (lane >> 2);
#pragma unroll
    for (int j2 = 0; j2 < 16; ++j2) {
        int d = j2 * 8 + ((lane & 3) << 1);
        uint32_t hh, ll;
        split2(acc_o[j2][0] * i0, acc_o[j2][1] * i0, hh, ll);
        *(uint32_t*)(Ah + (size_t)sr * HD_ + d)           = hh;
        *(uint32_t*)(Ah + LO_QKVA + (size_t)sr * HD_ + d) = ll;
        split2(acc_o[j2][2] * i1, acc_o[j2][3] * i1, hh, ll);
        *(uint32_t*)(Ah + (size_t)(sr + 8) * HD_ + d)           = hh;
        *(uint32_t*)(Ah + LO_QKVA + (size_t)(sr + 8) * HD_ + d) = ll;
    }
}

// ---------------------------------------------------------------------------
// Kernel 3: out = gather(attn) @ W_O + b_O (EXACT R8).  grid (16, 32)
// ---------------------------------------------------------------------------
__global__ __launch_bounds__(256)
void out_mma(const float* __restrict__ bo, float* __restrict__ out) {
    extern __shared__ char smem[];
    const int tid = threadIdx.x, lane = tid & 31, wid = tid >> 5;
    const int wm = (wid >> 2) * 64, wn = (wid & 3) * 32;
    const int n0 = blockIdx.x * 128, m0 = blockIdx.y * 128;
    const int bb = m0 >> 11, s0 = m0 & (S_ - 1);

    float acc[4][4][4];
    gemm_run2<64>(smem, tid,
        [&](int it) {
            int h = it >> 2, dbase = (it & 3) * 32;
            return &g_at2[0][((size_t)(bb * NH_ + h) * S_ + s0) * HD_ + dbase];
        }, (size_t)HD_, LO_QKVA,
        [&](int it) { return &g_wt2[3][0][(size_t)n0 * H_ + it * 32]; }, (size_t)H_, (size_t)H_ * H_,
        acc);

#pragma unroll
    for (int i = 0; i < 4; ++i)
#pragma unroll
        for (int j = 0; j < 4; ++j)
#pragma unroll
            for (int hf = 0; hf < 2; ++hf) {
                int m = m0 + wm + i * 16 + (lane >> 2) + hf * 8;
                int n = n0 + wn + j * 8 + ((lane & 3) << 1);
                float2 v = make_float2(acc[i][j][hf * 2] + bo[n],
                                       acc[i][j][hf * 2 + 1] + bo[n + 1]);
                *(float2*)(out + (size_t)m * H_ + n) = v;
            }
}

// ---------------------------------------------------------------------------
// Launch
// ---------------------------------------------------------------------------
extern "C" void kernel_launch(void* const* d_in, const int* in_sizes, int n_in,
                              void* d_out, int out_size) {
    const float* batch = (const float*)d_in[0];
    const float* mask  = (const float*)d_in[1];
    const float* wq = (const float*)d_in[2]; const float* bq = (const float*)d_in[3];
    const float* wk = (const float*)d_in[4]; const float* bk = (const float*)d_in[5];
    const float* wv = (const float*)d_in[6]; const float* bv = (const float*)d_in[7];
    const float* wo = (const float*)d_in[8]; const float* bo = (const float*)d_in[9];
    float* out = (float*)d_out;

    cudaFuncSetAttribute(qkv_mma,    cudaFuncAttributeMaxDynamicSharedMemorySize, SMEM_G);
    cudaFuncSetAttribute(flash_attn, cudaFuncAttributeMaxDynamicSharedMemorySize, SMEM_F);
    cudaFuncSetAttribute(out_mma,    cudaFuncAttributeMaxDynamicSharedMemorySize, SMEM_G);

    int prep_blocks = (int)(((size_t)M_ * H_ / 4 + 255) / 256);
    prep_x<<<prep_blocks, 256>>>(batch);
    transpose_w<<<dim3(64, 64, 4), dim3(32, 8)>>>(wq, wk, wv, wo);
    qkv_mma<<<dim3(16, 32, 3), 256, SMEM_G>>>(bq, bk, bv);
    flash_attn<<<dim3(16, 32), 256, SMEM_F>>>(mask);
    out_mma<<<dim3(16, 32), 256, SMEM_G>>>(bo, out);
}